// round 9
// baseline (speedup 1.0000x reference)
#include <cuda_runtime.h>
#include <cuda_bf16.h>
#include <math.h>
#include <stdint.h>

#define BB 2
#define SS 2048
#define EE 768
#define HH 12
#define DD 64
#define MT (BB*SS)

// ---------------------------------------------------------------------------
// Scratch (allocation-free rule: __device__ globals)
// ---------------------------------------------------------------------------
__device__ __nv_bfloat16 g_ah[(size_t)MT*EE];
__device__ __nv_bfloat16 g_al[(size_t)MT*EE];
__device__ __nv_bfloat16 g_wth[(size_t)4*EE*EE];   // [4][n][k] = W[k][n] hi
__device__ __nv_bfloat16 g_wtl[(size_t)4*EE*EE];   // lo
__device__ __nv_bfloat16 g_qh[(size_t)BB*HH*SS*DD];
__device__ __nv_bfloat16 g_ql[(size_t)BB*HH*SS*DD];
__device__ __nv_bfloat16 g_kh[(size_t)BB*HH*SS*DD];
__device__ __nv_bfloat16 g_kl[(size_t)BB*HH*SS*DD];
__device__ __nv_bfloat16 g_vh[(size_t)BB*HH*SS*DD];
__device__ __nv_bfloat16 g_vl[(size_t)BB*HH*SS*DD];

// ---------------------------------------------------------------------------
// PTX helpers (BASE ISA ONLY — harness ptxas targets sm_103 without 'a')
// ---------------------------------------------------------------------------
__device__ __forceinline__ uint32_t smem_u32(const void* p) {
    uint32_t a;
    asm("{ .reg .u64 t; cvta.to.shared.u64 t, %1; cvt.u32.u64 %0, t; }"
        : "=r"(a) : "l"(p));
    return a;
}
__device__ __forceinline__ void cp_async16(uint32_t saddr, const void* gaddr) {
    asm volatile("cp.async.cg.shared.global [%0], [%1], 16;"
                 :: "r"(saddr), "l"(gaddr) : "memory");
}
__device__ __forceinline__ void cp_commit() {
    asm volatile("cp.async.commit_group;" ::: "memory");
}
__device__ __forceinline__ void cp_wait1() {
    asm volatile("cp.async.wait_group 1;" ::: "memory");
}
__device__ __forceinline__ void cp_wait0() {
    asm volatile("cp.async.wait_group 0;" ::: "memory");
}
__device__ __forceinline__ void ldsm_x4(uint32_t* r, uint32_t addr) {
    asm volatile("ldmatrix.sync.aligned.m8n8.x4.shared.b16 {%0,%1,%2,%3}, [%4];"
                 : "=r"(r[0]), "=r"(r[1]), "=r"(r[2]), "=r"(r[3]) : "r"(addr));
}
__device__ __forceinline__ void ldsm_x4_t(uint32_t* r, uint32_t addr) {
    asm volatile("ldmatrix.sync.aligned.m8n8.x4.trans.shared.b16 {%0,%1,%2,%3}, [%4];"
                 : "=r"(r[0]), "=r"(r[1]), "=r"(r[2]), "=r"(r[3]) : "r"(addr));
}
__device__ __forceinline__ void mma16816(float* c, const uint32_t* a,
                                         uint32_t b0, uint32_t b1) {
    asm volatile(
        "mma.sync.aligned.m16n8k16.row.col.f32.bf16.bf16.f32 "
        "{%0,%1,%2,%3}, {%4,%5,%6,%7}, {%8,%9}, {%0,%1,%2,%3};"
        : "+f"(c[0]), "+f"(c[1]), "+f"(c[2]), "+f"(c[3])
        : "r"(a[0]), "r"(a[1]), "r"(a[2]), "r"(a[3]), "r"(b0), "r"(b1));
}
// split (p0,p1) into packed bf16 hi and bf16 lo (residual) registers
__device__ __forceinline__ void psplit(float p0, float p1,
                                       uint32_t& hreg, uint32_t& lreg) {
    __nv_bfloat162 hh = __float22bfloat162_rn(make_float2(p0, p1));
    float r0 = p0 - __bfloat162float(hh.x);
    float r1 = p1 - __bfloat162float(hh.y);
    __nv_bfloat162 ll = __float22bfloat162_rn(make_float2(r0, r1));
    hreg = *reinterpret_cast<uint32_t*>(&hh);
    lreg = *reinterpret_cast<uint32_t*>(&ll);
}
__device__ __forceinline__ void fsplit(float x, __nv_bfloat16& h, __nv_bfloat16& l) {
    h = __float2bfloat16(x);
    l = __float2bfloat16(x - __bfloat162float(h));
}

// ---------------------------------------------------------------------------
// Precision-split conversion: x -> (bf16 hi, bf16 lo)
// ---------------------------------------------------------------------------
__global__ __launch_bounds__(256)
void split_convert(const float* __restrict__ in, __nv_bfloat16* __restrict__ h,
                   __nv_bfloat16* __restrict__ l, int n)
{
    int i = blockIdx.x * blockDim.x + threadIdx.x;
    if (i < n) {
        float x = in[i];
        __nv_bfloat16 hi, lo;
        fsplit(x, hi, lo);
        h[i] = hi;
        l[i] = lo;
    }
}

// Transpose + split: Wt[z][n][k] = W_z[k][n]  (hi/lo bf16)
__global__ __launch_bounds__(256)
void transpose_split(const float* __restrict__ W0, const float* __restrict__ W1,
                     const float* __restrict__ W2, const float* __restrict__ W3,
                     __nv_bfloat16* __restrict__ th, __nv_bfloat16* __restrict__ tl)
{
    __shared__ float t[32][33];
    const float* W = (blockIdx.z == 0) ? W0 : (blockIdx.z == 1) ? W1
                   : (blockIdx.z == 2) ? W2 : W3;
    int n0 = blockIdx.x * 32, k0 = blockIdx.y * 32;
    int tx = threadIdx.x & 31, ty = threadIdx.x >> 5;
#pragma unroll
    for (int i = 0; i < 4; i++)
        t[ty + 8 * i][tx] = W[(size_t)(k0 + ty + 8 * i) * EE + n0 + tx];
    __syncthreads();
    size_t base = (size_t)blockIdx.z * EE * EE;
#pragma unroll
    for (int i = 0; i < 4; i++) {
        int row = ty + 8 * i;                 // local n
        float x = t[tx][row];                 // = W[k0+tx][n0+row]
        __nv_bfloat16 hi, lo;
        fsplit(x, hi, lo);
        size_t o = base + (size_t)(n0 + row) * EE + k0 + tx;
        th[o] = hi;
        tl[o] = lo;
    }
}

// ---------------------------------------------------------------------------
// mma.sync GEMM: C[M,768] = A[M,768] @ W[768,768] + bias  (bf16x3 split)
// CTA 128x128, 8 warps of 32x64, K-chunk 32, 2-stage cp.async, occupancy 2.
// MODE 0: fp32 C[m*EE+n] to fout.
// MODE 1: fused epilogue — bias + (RoPE via smem trig table + 0.125 scale for
//         q/k) + hi/lo split -> [B,H,S,D] bf16 pairs. The trig table is built
//         cooperatively into the (dead) cp.async stage buffers after mainloop.
// ---------------------------------------------------------------------------
#define KC 32
#define NCH (EE / KC)                 // 24
#define GM_PITCH 80                   // bytes per 32-bf16 row (padded from 64)
#define GM_TILE (128 * GM_PITCH)      // 10240
#define GM_BUF (4 * GM_TILE)          // Ah, Al, Bh, Bl
#define GM_SMEM (2 * GM_BUF)          // 81920 -> 2 CTAs/SM

template<int MODE>
__global__ __launch_bounds__(256, 2)
void gemm_mma(const __nv_bfloat16* __restrict__ Ah, const __nv_bfloat16* __restrict__ Al,
              const __nv_bfloat16* __restrict__ Wth, const __nv_bfloat16* __restrict__ Wtl,
              const float* b0, const float* b1, const float* b2, const float* b3,
              float* fout,
              __nv_bfloat16* qh, __nv_bfloat16* ql,
              __nv_bfloat16* kh, __nv_bfloat16* kl,
              __nv_bfloat16* vh, __nv_bfloat16* vl)
{
    extern __shared__ char smem[];
    const uint32_t sb = smem_u32(smem);
    const int tid = threadIdx.x;
    const int wid = tid >> 5, lane = tid & 31;
    const int wm = wid & 3;          // 4 m-groups of 32 rows
    const int wn = wid >> 2;         // 2 n-groups of 64 cols

    const int wsel = (MODE == 1) ? (int)blockIdx.z : 3;
    const float* bias = (wsel == 0) ? b0 : (wsel == 1) ? b1 : (wsel == 2) ? b2 : b3;
    const __nv_bfloat16* Bh = Wth + (size_t)wsel * EE * EE;
    const __nv_bfloat16* Bl = Wtl + (size_t)wsel * EE * EE;
    const int m0 = blockIdx.y * 128;
    const int n0 = blockIdx.x * 128;

    auto load_chunk = [&](int c) {
        uint32_t buf = sb + (uint32_t)(c & 1) * GM_BUF;
        int k0 = c * KC;
#pragma unroll
        for (int i = 0; i < 2; i++) {
            int idx = tid + i * 256;            // 0..511
            int row = idx >> 2;                 // 0..127
            int j   = idx & 3;                  // 16B quad
            uint32_t off = (uint32_t)(row * GM_PITCH + j * 16);
            size_t ga = (size_t)(m0 + row) * EE + k0 + j * 8;
            size_t gb = (size_t)(n0 + row) * EE + k0 + j * 8;
            cp_async16(buf + 0 * GM_TILE + off, Ah + ga);
            cp_async16(buf + 1 * GM_TILE + off, Al + ga);
            cp_async16(buf + 2 * GM_TILE + off, Bh + gb);
            cp_async16(buf + 3 * GM_TILE + off, Bl + gb);
        }
        cp_commit();
    };

    float acc[2][8][4];
#pragma unroll
    for (int mt = 0; mt < 2; mt++)
#pragma unroll
        for (int nt = 0; nt < 8; nt++)
#pragma unroll
            for (int i = 0; i < 4; i++) acc[mt][nt][i] = 0.f;

    load_chunk(0);
    load_chunk(1);

    const int rA = wm * 32 + (lane & 15);
    const int rB = wn * 64 + (lane & 15);
    const uint32_t chalf = (uint32_t)((lane >> 4) * 16);

    for (int c = 0; c < NCH; c++) {
        cp_wait1();            // chunk c resident
        __syncthreads();
        uint32_t buf = sb + (uint32_t)(c & 1) * GM_BUF;

#pragma unroll
        for (int ks = 0; ks < 2; ks++) {
            uint32_t colo = (uint32_t)(ks * 32) + chalf;
            uint32_t ah[2][4], al[2][4], bh[4][4], bl[4][4];
#pragma unroll
            for (int mt = 0; mt < 2; mt++) {
                uint32_t off = (uint32_t)((rA + mt * 16) * GM_PITCH) + colo;
                ldsm_x4(ah[mt], buf + 0 * GM_TILE + off);
                ldsm_x4(al[mt], buf + 1 * GM_TILE + off);
            }
#pragma unroll
            for (int p = 0; p < 4; p++) {
                uint32_t off = (uint32_t)((rB + p * 16) * GM_PITCH) + colo;
                ldsm_x4(bh[p], buf + 2 * GM_TILE + off);
                ldsm_x4(bl[p], buf + 3 * GM_TILE + off);
            }
#pragma unroll
            for (int mt = 0; mt < 2; mt++)
#pragma unroll
                for (int nt = 0; nt < 8; nt++) {
                    const int p = nt >> 1, q = nt & 1;
                    mma16816(acc[mt][nt], ah[mt], bh[p][q], bh[p][q + 2]);
                    mma16816(acc[mt][nt], ah[mt], bl[p][q], bl[p][q + 2]);
                    mma16816(acc[mt][nt], al[mt], bh[p][q], bh[p][q + 2]);
                }
        }

        __syncthreads();       // all warps done reading slot c&1
        if (c + 2 < NCH) load_chunk(c + 2);
        else cp_commit();
    }

    if (MODE == 0) {
        // plain fp32 epilogue (output projection -> d_out)
        const int mrow0 = m0 + wm * 32;
#pragma unroll
        for (int mt = 0; mt < 2; mt++) {
#pragma unroll
            for (int nt = 0; nt < 8; nt++) {
                int gn = n0 + wn * 64 + nt * 8 + 2 * (lane & 3);
                float2 bv = *(const float2*)&bias[gn];
                int r0 = mrow0 + mt * 16 + (lane >> 2);
                float2 v0 = { acc[mt][nt][0] + bv.x, acc[mt][nt][1] + bv.y };
                float2 v1 = { acc[mt][nt][2] + bv.x, acc[mt][nt][3] + bv.y };
                *(float2*)&fout[(size_t)r0 * EE + gn] = v0;
                *(float2*)&fout[(size_t)(r0 + 8) * EE + gn] = v1;
            }
        }
    } else {
        // fused bias + RoPE + scale + split epilogue
        __nv_bfloat16 *dh, *dl;
        if (wsel == 0)      { dh = qh; dl = ql; }
        else if (wsel == 1) { dh = kh; dl = kl; }
        else                { dh = vh; dl = vl; }
        const int hh = (int)blockIdx.x * 2 + wn;     // head index
        const int c2 = 2 * (lane & 3);
        const float RC = 0.28782313662425572f;       // ln(10000)/32

        float2* tab = (float2*)smem;                 // reuse dead stage buffers
        if (wsel < 2) {
            cp_wait0();
            __syncthreads();                         // stage buffers now dead
            for (int idx = tid; idx < 128 * 32; idx += 256) {
                int rl = idx >> 5, i = idx & 31;
                int s = (m0 + rl) & (SS - 1);
                float ang = (float)s * expf(-(float)i * RC);
                float sn, cs;
                sincosf(ang, &sn, &cs);
                tab[idx] = make_float2(cs, sn);
            }
            __syncthreads();
        }

#pragma unroll
        for (int mt = 0; mt < 2; mt++) {
#pragma unroll
            for (int rr = 0; rr < 2; rr++) {
                int rloc = wm * 32 + mt * 16 + (lane >> 2) + rr * 8;
                int r = m0 + rloc;
                int b_ = r >> 11, s = r & (SS - 1);
                float vals[8][2];
#pragma unroll
                for (int nt = 0; nt < 8; nt++) {
                    float2 bv = *(const float2*)&bias[hh * 64 + nt * 8 + c2];
                    vals[nt][0] = acc[mt][nt][2 * rr]     + bv.x;
                    vals[nt][1] = acc[mt][nt][2 * rr + 1] + bv.y;
                }
                if (wsel < 2) {
#pragma unroll
                    for (int nt = 0; nt < 4; nt++) {
#pragma unroll
                        for (int cc = 0; cc < 2; cc++) {
                            int i = nt * 8 + c2 + cc;
                            float2 cs = tab[rloc * 32 + i];
                            float x = vals[nt][cc], y = vals[nt + 4][cc];
                            vals[nt][cc]     = x * cs.x - y * cs.y;
                            vals[nt + 4][cc] = y * cs.x + x * cs.y;
                        }
                    }
                    if (wsel == 0) {
#pragma unroll
                        for (int nt = 0; nt < 8; nt++) {
                            vals[nt][0] *= 0.125f;
                            vals[nt][1] *= 0.125f;
                        }
                    }
                }
                size_t rowb = ((size_t)(b_ * HH + hh) * SS + s) * DD;
#pragma unroll
                for (int nt = 0; nt < 8; nt++) {
                    uint32_t hreg, lreg;
                    psplit(vals[nt][0], vals[nt][1], hreg, lreg);
                    *(uint32_t*)&dh[rowb + nt * 8 + c2] = hreg;
                    *(uint32_t*)&dl[rowb + nt * 8 + c2] = lreg;
                }
            }
        }
    }
}

// ---------------------------------------------------------------------------
// Tensor-core causal flash attention (bf16x3 split, mma.sync).
// CTA = 128 Q rows x one (b,h); 8 warps x 16 rows (softmax warp-local).
// K/V tiles of 128 double-buffered via cp.async (fewer syncs / softmax
// sections than 64). Diagonal tiles skip fully-masked 16-col strips.
// Output written directly as split bf16 (feeds the output-projection GEMM).
// ---------------------------------------------------------------------------
#define AT_PITCH 144                      // 64 bf16 = 128B data + 16B pad
#define AT_Q (128 * AT_PITCH)             // 18432 per Q tile (hi or lo)
#define AT_KV (128 * AT_PITCH)            // 18432 per K/V tile (128 rows)
#define AT_STAGE (4 * AT_KV)              // Kh,Kl,Vh,Vl = 73728
#define AT_SMEM (2 * AT_Q + 2 * AT_STAGE) // 184320

__global__ __launch_bounds__(256)
void attn_mma(const __nv_bfloat16* __restrict__ qh, const __nv_bfloat16* __restrict__ ql,
              const __nv_bfloat16* __restrict__ kh, const __nv_bfloat16* __restrict__ kl,
              const __nv_bfloat16* __restrict__ vh, const __nv_bfloat16* __restrict__ vl,
              __nv_bfloat16* __restrict__ oh, __nv_bfloat16* __restrict__ ol)
{
    extern __shared__ char smem[];
    const uint32_t sb = smem_u32(smem);
    const int tid = threadIdx.x;
    const int wid = tid >> 5, lane = tid & 31;

    const int mtile = (int)(gridDim.x - 1 - blockIdx.x);   // heavy CTAs first
    const int bh = blockIdx.y;
    const int m0 = mtile * 128;
    const int ntmax = mtile;               // 128-wide KV tiles, causal
    const size_t hbase = (size_t)bh * SS * DD;
    const __nv_bfloat16* qhp = qh + hbase;
    const __nv_bfloat16* qlp = ql + hbase;
    const __nv_bfloat16* khp = kh + hbase;
    const __nv_bfloat16* klp = kl + hbase;
    const __nv_bfloat16* vhp = vh + hbase;
    const __nv_bfloat16* vlp = vl + hbase;

    // ---- load Q tile (hi+lo) ----
#pragma unroll
    for (int i = 0; i < 4; i++) {
        int cid = tid + i * 256;           // 0..1023
        int row = cid >> 3;
        int j   = cid & 7;
        uint32_t off = (uint32_t)(row * AT_PITCH + j * 16);
        size_t g = (size_t)(m0 + row) * DD + j * 8;
        cp_async16(sb + off, qhp + g);
        cp_async16(sb + AT_Q + off, qlp + g);
    }
    cp_commit();

    auto load_kv = [&](int t) {
        if (t <= ntmax) {
            uint32_t base = sb + 2 * AT_Q + (uint32_t)(t & 1) * AT_STAGE;
            int n0 = t * 128;
#pragma unroll
            for (int i = 0; i < 4; i++) {
                int cid = tid + i * 256;       // 0..1023
                int row = cid >> 3;
                int j   = cid & 7;
                uint32_t off = (uint32_t)(row * AT_PITCH + j * 16);
                size_t g = (size_t)(n0 + row) * DD + j * 8;
                cp_async16(base + 0 * AT_KV + off, khp + g);
                cp_async16(base + 1 * AT_KV + off, klp + g);
                cp_async16(base + 2 * AT_KV + off, vhp + g);
                cp_async16(base + 3 * AT_KV + off, vlp + g);
            }
        }
        cp_commit();
    };
    load_kv(0);
    load_kv(1);

    float oacc[8][4];
#pragma unroll
    for (int d = 0; d < 8; d++)
#pragma unroll
        for (int j = 0; j < 4; j++) oacc[d][j] = 0.f;
    float mi0 = -1e30f, mi1 = -1e30f, li0 = 0.f, li1 = 0.f;
    uint32_t qfh[4][4], qfl[4][4];

    const int wr0 = m0 + wid * 16;     // warp's first global Q row

    for (int nt = 0; nt <= ntmax; nt++) {
        cp_wait1();
        __syncthreads();               // stage nt (and Q at nt=0) visible

        if (nt == 0) {                 // load Q fragments once
#pragma unroll
            for (int kc = 0; kc < 4; kc++) {
                uint32_t a = sb + (uint32_t)((wid * 16 + (lane & 15)) * AT_PITCH)
                           + (uint32_t)(kc * 32) + (uint32_t)((lane >> 4) * 16);
                ldsm_x4(qfh[kc], a);
                ldsm_x4(qfl[kc], a + AT_Q);
            }
        }

        const int n0 = nt * 128;
        const bool diag = (nt == ntmax) && (ntmax == mtile);  // n0 == m0
        const int climit = wr0 + 15;   // last valid column for this warp
        const uint32_t kvb = sb + 2 * AT_Q + (uint32_t)(nt & 1) * AT_STAGE;

        // ---- S = Q K^T (3-term split), 16 col-strips of 8 ----
        float sacc[16][4];
#pragma unroll
        for (int t8 = 0; t8 < 16; t8++)
#pragma unroll
            for (int j = 0; j < 4; j++) sacc[t8][j] = 0.f;

#pragma unroll
        for (int kc = 0; kc < 4; kc++) {
            uint32_t colo = (uint32_t)(kc * 32) + (uint32_t)((lane >> 4) * 16);
#pragma unroll
            for (int st = 0; st < 8; st++) {
                if (!diag || n0 + st * 16 <= climit) {
                    uint32_t a = kvb + (uint32_t)((st * 16 + (lane & 15)) * AT_PITCH) + colo;
                    uint32_t k4h[4], k4l[4];
                    ldsm_x4(k4h, a);
                    ldsm_x4(k4l, a + AT_KV);
                    mma16816(sacc[2 * st],     qfh[kc], k4h[0], k4h[2]);
                    mma16816(sacc[2 * st],     qfh[kc], k4l[0], k4l[2]);
                    mma16816(sacc[2 * st],     qfl[kc], k4h[0], k4h[2]);
                    mma16816(sacc[2 * st + 1], qfh[kc], k4h[1], k4h[3]);
                    mma16816(sacc[2 * st + 1], qfh[kc], k4l[1], k4l[3]);
                    mma16816(sacc[2 * st + 1], qfl[kc], k4h[1], k4h[3]);
                }
            }
        }

        // ---- causal mask (diagonal tile only; skipped strips become -inf) ----
        const int rr0 = wr0 + (lane >> 2);
        if (diag) {
#pragma unroll
            for (int t8 = 0; t8 < 16; t8++) {
                int c0 = n0 + t8 * 8 + 2 * (lane & 3);
                if (c0     > rr0)     sacc[t8][0] = -1e30f;
                if (c0 + 1 > rr0)     sacc[t8][1] = -1e30f;
                if (c0     > rr0 + 8) sacc[t8][2] = -1e30f;
                if (c0 + 1 > rr0 + 8) sacc[t8][3] = -1e30f;
            }
        }

        // ---- online softmax (rows lane/4 and lane/4+8) ----
        float mx0 = -1e30f, mx1 = -1e30f;
#pragma unroll
        for (int t8 = 0; t8 < 16; t8++) {
            mx0 = fmaxf(mx0, fmaxf(sacc[t8][0], sacc[t8][1]));
            mx1 = fmaxf(mx1, fmaxf(sacc[t8][2], sacc[t8][3]));
        }
        mx0 = fmaxf(mx0, __shfl_xor_sync(0xffffffffu, mx0, 1));
        mx0 = fmaxf(mx0, __shfl_xor_sync(0xffffffffu, mx0, 2));
        mx1 = fmaxf(mx1, __shfl_xor_sync(0xffffffffu, mx1, 1));
        mx1 = fmaxf(mx1, __shfl_xor_sync(0xffffffffu, mx1, 2));
        float mn0 = fmaxf(mi0, mx0), mn1 = fmaxf(mi1, mx1);
        float al0 = __expf(mi0 - mn0), al1 = __expf(mi1 - mn1);
        mi0 = mn0; mi1 = mn1;
        float s0 = 0.f, s1 = 0.f;
#pragma unroll
        for (int t8 = 0; t8 < 16; t8++) {
            float p0 = __expf(sacc[t8][0] - mn0);
            float p1 = __expf(sacc[t8][1] - mn0);
            float p2 = __expf(sacc[t8][2] - mn1);
            float p3 = __expf(sacc[t8][3] - mn1);
            sacc[t8][0] = p0; sacc[t8][1] = p1;
            sacc[t8][2] = p2; sacc[t8][3] = p3;
            s0 += p0 + p1; s1 += p2 + p3;
        }
        li0 = li0 * al0 + s0;        // lane-partial row sums
        li1 = li1 * al1 + s1;
#pragma unroll
        for (int d = 0; d < 8; d++) {
            oacc[d][0] *= al0; oacc[d][1] *= al0;
            oacc[d][2] *= al1; oacc[d][3] *= al1;
        }

        // ---- P -> bf16 hi/lo A-fragments (S-frag layout == A-frag layout) ----
        uint32_t aPh[8][4], aPl[8][4];
#pragma unroll
        for (int kc = 0; kc < 8; kc++) {
            psplit(sacc[2 * kc][0],     sacc[2 * kc][1],     aPh[kc][0], aPl[kc][0]);
            psplit(sacc[2 * kc][2],     sacc[2 * kc][3],     aPh[kc][1], aPl[kc][1]);
            psplit(sacc[2 * kc + 1][0], sacc[2 * kc + 1][1], aPh[kc][2], aPl[kc][2]);
            psplit(sacc[2 * kc + 1][2], sacc[2 * kc + 1][3], aPh[kc][3], aPl[kc][3]);
        }

        // ---- O += P V (3-term split, V via ldmatrix.trans) ----
        const uint32_t vbb = kvb + 2 * AT_KV;
#pragma unroll
        for (int kc = 0; kc < 8; kc++) {
            if (!diag || n0 + kc * 16 <= climit) {   // P strip all-zero otherwise
#pragma unroll
                for (int vp = 0; vp < 4; vp++) {
                    uint32_t a = vbb + (uint32_t)((kc * 16 + (lane & 15)) * AT_PITCH)
                               + (uint32_t)(vp * 32) + (uint32_t)((lane >> 4) * 16);
                    uint32_t v4h[4], v4l[4];
                    ldsm_x4_t(v4h, a);
                    ldsm_x4_t(v4l, a + AT_KV);
                    mma16816(oacc[2 * vp],     aPh[kc], v4h[0], v4h[1]);
                    mma16816(oacc[2 * vp],     aPl[kc], v4h[0], v4h[1]);
                    mma16816(oacc[2 * vp],     aPh[kc], v4l[0], v4l[1]);
                    mma16816(oacc[2 * vp + 1], aPh[kc], v4h[2], v4h[3]);
                    mma16816(oacc[2 * vp + 1], aPl[kc], v4h[2], v4h[3]);
                    mma16816(oacc[2 * vp + 1], aPh[kc], v4l[2], v4l[3]);
                }
            }
        }

        __syncthreads();               // all warps done reading slot nt&1
        load_kv(nt + 2);
    }

    // ---- normalize + write split bf16 output [m][E] at cols h*64.. ----
    li0 += __shfl_xor_sync(0xffffffffu, li0, 1);
    li0 += __shfl_xor_sync(0xffffffffu, li0, 2);
    li1 += __shfl_xor_sync(0xffffffffu, li1, 1);
    li1 += __shfl_xor_sync(0xffffffffu, li1, 2);
    const float inv0 = 1.f / li0, inv1 = 1.f / li1;

    const int b_ = bh / HH, h_ = bh % HH;
    const int r0g = m0 + wid * 16 + (lane >> 2);
#pragma unroll
    for (int dt = 0; dt < 8; dt++) {
        int col = h_ * 64 + dt * 8 + 2 * (lane & 3);
        size_t o0 = (size_t)(b_ * SS + r0g) * EE + col;
        size_t o1 = (size_t)(b_ * SS + r0g + 8) * EE + col;
        uint32_t hreg, lreg;
        psplit(oacc[dt][0] * inv0, oacc[dt][1] * inv0, hreg, lreg);
        *(uint32_t*)&oh[o0] = hreg;
        *(uint32_t*)&ol[o0] = lreg;
        psplit(oacc[dt][2] * inv1, oacc[dt][3] * inv1, hreg, lreg);
        *(uint32_t*)&oh[o1] = hreg;
        *(uint32_t*)&ol[o1] = lreg;
    }
}

// ---------------------------------------------------------------------------
extern "C" void kernel_launch(void* const* d_in, const int* in_sizes, int n_in,
                              void* d_out, int out_size)
{
    (void)in_sizes; (void)n_in; (void)out_size;
    const float* x  = (const float*)d_in[0];
    const float* Wq = (const float*)d_in[1];
    const float* bq = (const float*)d_in[2];
    const float* Wk = (const float*)d_in[3];
    const float* bk = (const float*)d_in[4];
    const float* Wv = (const float*)d_in[5];
    const float* bv = (const float*)d_in[6];
    const float* Wp = (const float*)d_in[7];
    const float* bp = (const float*)d_in[8];

    __nv_bfloat16 *ah, *al, *wth, *wtl, *qh, *ql, *kh, *kl, *vh, *vl;
    cudaGetSymbolAddress((void**)&ah,  g_ah);
    cudaGetSymbolAddress((void**)&al,  g_al);
    cudaGetSymbolAddress((void**)&wth, g_wth);
    cudaGetSymbolAddress((void**)&wtl, g_wtl);
    cudaGetSymbolAddress((void**)&qh,  g_qh);
    cudaGetSymbolAddress((void**)&ql,  g_ql);
    cudaGetSymbolAddress((void**)&kh,  g_kh);
    cudaGetSymbolAddress((void**)&kl,  g_kl);
    cudaGetSymbolAddress((void**)&vh,  g_vh);
    cudaGetSymbolAddress((void**)&vl,  g_vl);

    cudaFuncSetAttribute(gemm_mma<1>,
                         cudaFuncAttributeMaxDynamicSharedMemorySize, GM_SMEM);
    cudaFuncSetAttribute(gemm_mma<0>,
                         cudaFuncAttributeMaxDynamicSharedMemorySize, GM_SMEM);
    cudaFuncSetAttribute(attn_mma,
                         cudaFuncAttributeMaxDynamicSharedMemorySize, AT_SMEM);

    // Split x and all 4 weight matrices into bf16 hi/lo (weights transposed)
    split_convert<<<(MT * EE + 255) / 256, 256>>>(x, ah, al, MT * EE);
    transpose_split<<<dim3(EE / 32, EE / 32, 4), 256>>>(Wq, Wk, Wv, Wp, wth, wtl);

    // Fused Q/K/V projections + bias + RoPE + scale + split -> bf16 [B,H,S,D]
    gemm_mma<1><<<dim3(EE / 128, MT / 128, 3), 256, GM_SMEM>>>(
        ah, al, wth, wtl, bq, bk, bv, nullptr, nullptr,
        qh, ql, kh, kl, vh, vl);

    // Tensor-core causal flash attention -> split bf16 [B,S,E] (into ah/al)
    attn_mma<<<dim3(SS / 128, BB * HH), 256, AT_SMEM>>>(
        qh, ql, kh, kl, vh, vl, ah, al);

    // Output projection -> d_out
    gemm_mma<0><<<dim3(EE / 128, MT / 128, 1), 256, GM_SMEM>>>(
        ah, al, wth, wtl, nullptr, nullptr, nullptr, bp, (float*)d_out,
        nullptr, nullptr, nullptr, nullptr, nullptr, nullptr);
}

// round 10
// speedup vs baseline: 1.1520x; 1.1520x over previous
#include <cuda_runtime.h>
#include <cuda_bf16.h>
#include <math.h>
#include <stdint.h>

#define BB 2
#define SS 2048
#define EE 768
#define HH 12
#define DD 64
#define MT (BB*SS)

// ---------------------------------------------------------------------------
// Scratch (allocation-free rule: __device__ globals)
// ---------------------------------------------------------------------------
__device__ __nv_bfloat16 g_ah[(size_t)MT*EE];
__device__ __nv_bfloat16 g_al[(size_t)MT*EE];
__device__ __nv_bfloat16 g_wth[(size_t)4*EE*EE];   // [4][n][k] = W[k][n] hi
__device__ __nv_bfloat16 g_wtl[(size_t)4*EE*EE];   // lo
__device__ __nv_bfloat16 g_qh[(size_t)BB*HH*SS*DD];
__device__ __nv_bfloat16 g_ql[(size_t)BB*HH*SS*DD];
__device__ __nv_bfloat16 g_kh[(size_t)BB*HH*SS*DD];
__device__ __nv_bfloat16 g_kl[(size_t)BB*HH*SS*DD];
__device__ __nv_bfloat16 g_vh[(size_t)BB*HH*SS*DD];
__device__ __nv_bfloat16 g_vl[(size_t)BB*HH*SS*DD];

// ---------------------------------------------------------------------------
// PTX helpers (BASE ISA ONLY — harness ptxas targets sm_103 without 'a')
// ---------------------------------------------------------------------------
__device__ __forceinline__ uint32_t smem_u32(const void* p) {
    uint32_t a;
    asm("{ .reg .u64 t; cvta.to.shared.u64 t, %1; cvt.u32.u64 %0, t; }"
        : "=r"(a) : "l"(p));
    return a;
}
__device__ __forceinline__ void cp_async16(uint32_t saddr, const void* gaddr) {
    asm volatile("cp.async.cg.shared.global [%0], [%1], 16;"
                 :: "r"(saddr), "l"(gaddr) : "memory");
}
__device__ __forceinline__ void cp_commit() {
    asm volatile("cp.async.commit_group;" ::: "memory");
}
__device__ __forceinline__ void cp_wait1() {
    asm volatile("cp.async.wait_group 1;" ::: "memory");
}
__device__ __forceinline__ void cp_wait0() {
    asm volatile("cp.async.wait_group 0;" ::: "memory");
}
__device__ __forceinline__ void ldsm_x4(uint32_t* r, uint32_t addr) {
    asm volatile("ldmatrix.sync.aligned.m8n8.x4.shared.b16 {%0,%1,%2,%3}, [%4];"
                 : "=r"(r[0]), "=r"(r[1]), "=r"(r[2]), "=r"(r[3]) : "r"(addr));
}
__device__ __forceinline__ void ldsm_x4_t(uint32_t* r, uint32_t addr) {
    asm volatile("ldmatrix.sync.aligned.m8n8.x4.trans.shared.b16 {%0,%1,%2,%3}, [%4];"
                 : "=r"(r[0]), "=r"(r[1]), "=r"(r[2]), "=r"(r[3]) : "r"(addr));
}
__device__ __forceinline__ void mma16816(float* c, const uint32_t* a,
                                         uint32_t b0, uint32_t b1) {
    asm volatile(
        "mma.sync.aligned.m16n8k16.row.col.f32.bf16.bf16.f32 "
        "{%0,%1,%2,%3}, {%4,%5,%6,%7}, {%8,%9}, {%0,%1,%2,%3};"
        : "+f"(c[0]), "+f"(c[1]), "+f"(c[2]), "+f"(c[3])
        : "r"(a[0]), "r"(a[1]), "r"(a[2]), "r"(a[3]), "r"(b0), "r"(b1));
}
// split (p0,p1) into packed bf16 hi and bf16 lo (residual) registers
__device__ __forceinline__ void psplit(float p0, float p1,
                                       uint32_t& hreg, uint32_t& lreg) {
    __nv_bfloat162 hh = __float22bfloat162_rn(make_float2(p0, p1));
    float r0 = p0 - __bfloat162float(hh.x);
    float r1 = p1 - __bfloat162float(hh.y);
    __nv_bfloat162 ll = __float22bfloat162_rn(make_float2(r0, r1));
    hreg = *reinterpret_cast<uint32_t*>(&hh);
    lreg = *reinterpret_cast<uint32_t*>(&ll);
}
__device__ __forceinline__ void fsplit(float x, __nv_bfloat16& h, __nv_bfloat16& l) {
    h = __float2bfloat16(x);
    l = __float2bfloat16(x - __bfloat162float(h));
}

// ---------------------------------------------------------------------------
// Precision-split conversion: x -> (bf16 hi, bf16 lo)
// ---------------------------------------------------------------------------
__global__ __launch_bounds__(256)
void split_convert(const float* __restrict__ in, __nv_bfloat16* __restrict__ h,
                   __nv_bfloat16* __restrict__ l, int n)
{
    int i = blockIdx.x * blockDim.x + threadIdx.x;
    if (i < n) {
        float x = in[i];
        __nv_bfloat16 hi, lo;
        fsplit(x, hi, lo);
        h[i] = hi;
        l[i] = lo;
    }
}

// Transpose + split: Wt[z][n][k] = W_z[k][n]  (hi/lo bf16)
__global__ __launch_bounds__(256)
void transpose_split(const float* __restrict__ W0, const float* __restrict__ W1,
                     const float* __restrict__ W2, const float* __restrict__ W3,
                     __nv_bfloat16* __restrict__ th, __nv_bfloat16* __restrict__ tl)
{
    __shared__ float t[32][33];
    const float* W = (blockIdx.z == 0) ? W0 : (blockIdx.z == 1) ? W1
                   : (blockIdx.z == 2) ? W2 : W3;
    int n0 = blockIdx.x * 32, k0 = blockIdx.y * 32;
    int tx = threadIdx.x & 31, ty = threadIdx.x >> 5;
#pragma unroll
    for (int i = 0; i < 4; i++)
        t[ty + 8 * i][tx] = W[(size_t)(k0 + ty + 8 * i) * EE + n0 + tx];
    __syncthreads();
    size_t base = (size_t)blockIdx.z * EE * EE;
#pragma unroll
    for (int i = 0; i < 4; i++) {
        int row = ty + 8 * i;                 // local n
        float x = t[tx][row];                 // = W[k0+tx][n0+row]
        __nv_bfloat16 hi, lo;
        fsplit(x, hi, lo);
        size_t o = base + (size_t)(n0 + row) * EE + k0 + tx;
        th[o] = hi;
        tl[o] = lo;
    }
}

// ---------------------------------------------------------------------------
// mma.sync GEMM: C[M,768] = A[M,768] @ W[768,768] + bias  (bf16x3 split)
// CTA 128x128, 8 warps of 32x64, K-chunk 32, 2-stage cp.async, occupancy 2.
// MODE 0: fp32 C[m*EE+n] to fout.
// MODE 1: fused epilogue — bias + (RoPE via smem trig table + 0.125 scale for
//         q/k) + hi/lo split -> [B,H,S,D] bf16 pairs.
// ---------------------------------------------------------------------------
#define KC 32
#define NCH (EE / KC)                 // 24
#define GM_PITCH 80                   // bytes per 32-bf16 row (padded from 64)
#define GM_TILE (128 * GM_PITCH)      // 10240
#define GM_BUF (4 * GM_TILE)          // Ah, Al, Bh, Bl
#define GM_SMEM (2 * GM_BUF)          // 81920 -> 2 CTAs/SM

template<int MODE>
__global__ __launch_bounds__(256, 2)
void gemm_mma(const __nv_bfloat16* __restrict__ Ah, const __nv_bfloat16* __restrict__ Al,
              const __nv_bfloat16* __restrict__ Wth, const __nv_bfloat16* __restrict__ Wtl,
              const float* b0, const float* b1, const float* b2, const float* b3,
              float* fout,
              __nv_bfloat16* qh, __nv_bfloat16* ql,
              __nv_bfloat16* kh, __nv_bfloat16* kl,
              __nv_bfloat16* vh, __nv_bfloat16* vl)
{
    extern __shared__ char smem[];
    const uint32_t sb = smem_u32(smem);
    const int tid = threadIdx.x;
    const int wid = tid >> 5, lane = tid & 31;
    const int wm = wid & 3;          // 4 m-groups of 32 rows
    const int wn = wid >> 2;         // 2 n-groups of 64 cols

    const int wsel = (MODE == 1) ? (int)blockIdx.z : 3;
    const float* bias = (wsel == 0) ? b0 : (wsel == 1) ? b1 : (wsel == 2) ? b2 : b3;
    const __nv_bfloat16* Bh = Wth + (size_t)wsel * EE * EE;
    const __nv_bfloat16* Bl = Wtl + (size_t)wsel * EE * EE;
    const int m0 = blockIdx.y * 128;
    const int n0 = blockIdx.x * 128;

    auto load_chunk = [&](int c) {
        uint32_t buf = sb + (uint32_t)(c & 1) * GM_BUF;
        int k0 = c * KC;
#pragma unroll
        for (int i = 0; i < 2; i++) {
            int idx = tid + i * 256;            // 0..511
            int row = idx >> 2;                 // 0..127
            int j   = idx & 3;                  // 16B quad
            uint32_t off = (uint32_t)(row * GM_PITCH + j * 16);
            size_t ga = (size_t)(m0 + row) * EE + k0 + j * 8;
            size_t gb = (size_t)(n0 + row) * EE + k0 + j * 8;
            cp_async16(buf + 0 * GM_TILE + off, Ah + ga);
            cp_async16(buf + 1 * GM_TILE + off, Al + ga);
            cp_async16(buf + 2 * GM_TILE + off, Bh + gb);
            cp_async16(buf + 3 * GM_TILE + off, Bl + gb);
        }
        cp_commit();
    };

    float acc[2][8][4];
#pragma unroll
    for (int mt = 0; mt < 2; mt++)
#pragma unroll
        for (int nt = 0; nt < 8; nt++)
#pragma unroll
            for (int i = 0; i < 4; i++) acc[mt][nt][i] = 0.f;

    load_chunk(0);
    load_chunk(1);

    const int rA = wm * 32 + (lane & 15);
    const int rB = wn * 64 + (lane & 15);
    const uint32_t chalf = (uint32_t)((lane >> 4) * 16);

    for (int c = 0; c < NCH; c++) {
        cp_wait1();            // chunk c resident
        __syncthreads();
        uint32_t buf = sb + (uint32_t)(c & 1) * GM_BUF;

#pragma unroll
        for (int ks = 0; ks < 2; ks++) {
            uint32_t colo = (uint32_t)(ks * 32) + chalf;
            uint32_t ah[2][4], al[2][4], bh[4][4], bl[4][4];
#pragma unroll
            for (int mt = 0; mt < 2; mt++) {
                uint32_t off = (uint32_t)((rA + mt * 16) * GM_PITCH) + colo;
                ldsm_x4(ah[mt], buf + 0 * GM_TILE + off);
                ldsm_x4(al[mt], buf + 1 * GM_TILE + off);
            }
#pragma unroll
            for (int p = 0; p < 4; p++) {
                uint32_t off = (uint32_t)((rB + p * 16) * GM_PITCH) + colo;
                ldsm_x4(bh[p], buf + 2 * GM_TILE + off);
                ldsm_x4(bl[p], buf + 3 * GM_TILE + off);
            }
#pragma unroll
            for (int mt = 0; mt < 2; mt++)
#pragma unroll
                for (int nt = 0; nt < 8; nt++) {
                    const int p = nt >> 1, q = nt & 1;
                    mma16816(acc[mt][nt], ah[mt], bh[p][q], bh[p][q + 2]);
                    mma16816(acc[mt][nt], ah[mt], bl[p][q], bl[p][q + 2]);
                    mma16816(acc[mt][nt], al[mt], bh[p][q], bh[p][q + 2]);
                }
        }

        __syncthreads();       // all warps done reading slot c&1
        if (c + 2 < NCH) load_chunk(c + 2);
        else cp_commit();
    }

    if (MODE == 0) {
        // plain fp32 epilogue (output projection -> d_out)
        const int mrow0 = m0 + wm * 32;
#pragma unroll
        for (int mt = 0; mt < 2; mt++) {
#pragma unroll
            for (int nt = 0; nt < 8; nt++) {
                int gn = n0 + wn * 64 + nt * 8 + 2 * (lane & 3);
                float2 bv = *(const float2*)&bias[gn];
                int r0 = mrow0 + mt * 16 + (lane >> 2);
                float2 v0 = { acc[mt][nt][0] + bv.x, acc[mt][nt][1] + bv.y };
                float2 v1 = { acc[mt][nt][2] + bv.x, acc[mt][nt][3] + bv.y };
                *(float2*)&fout[(size_t)r0 * EE + gn] = v0;
                *(float2*)&fout[(size_t)(r0 + 8) * EE + gn] = v1;
            }
        }
    } else {
        // fused bias + RoPE + scale + split epilogue
        __nv_bfloat16 *dh, *dl;
        if (wsel == 0)      { dh = qh; dl = ql; }
        else if (wsel == 1) { dh = kh; dl = kl; }
        else                { dh = vh; dl = vl; }
        const int hh = (int)blockIdx.x * 2 + wn;     // head index
        const int c2 = 2 * (lane & 3);
        const float RC = 0.28782313662425572f;       // ln(10000)/32

        float2* tab = (float2*)smem;                 // reuse dead stage buffers
        if (wsel < 2) {
            cp_wait0();
            __syncthreads();                         // stage buffers now dead
            for (int idx = tid; idx < 128 * 32; idx += 256) {
                int rl = idx >> 5, i = idx & 31;
                int s = (m0 + rl) & (SS - 1);
                float ang = (float)s * expf(-(float)i * RC);
                float sn, cs;
                sincosf(ang, &sn, &cs);
                tab[idx] = make_float2(cs, sn);
            }
            __syncthreads();
        }

#pragma unroll
        for (int mt = 0; mt < 2; mt++) {
#pragma unroll
            for (int rr = 0; rr < 2; rr++) {
                int rloc = wm * 32 + mt * 16 + (lane >> 2) + rr * 8;
                int r = m0 + rloc;
                int b_ = r >> 11, s = r & (SS - 1);
                float vals[8][2];
#pragma unroll
                for (int nt = 0; nt < 8; nt++) {
                    float2 bv = *(const float2*)&bias[hh * 64 + nt * 8 + c2];
                    vals[nt][0] = acc[mt][nt][2 * rr]     + bv.x;
                    vals[nt][1] = acc[mt][nt][2 * rr + 1] + bv.y;
                }
                if (wsel < 2) {
#pragma unroll
                    for (int nt = 0; nt < 4; nt++) {
#pragma unroll
                        for (int cc = 0; cc < 2; cc++) {
                            int i = nt * 8 + c2 + cc;
                            float2 cs = tab[rloc * 32 + i];
                            float x = vals[nt][cc], y = vals[nt + 4][cc];
                            vals[nt][cc]     = x * cs.x - y * cs.y;
                            vals[nt + 4][cc] = y * cs.x + x * cs.y;
                        }
                    }
                    if (wsel == 0) {
#pragma unroll
                        for (int nt = 0; nt < 8; nt++) {
                            vals[nt][0] *= 0.125f;
                            vals[nt][1] *= 0.125f;
                        }
                    }
                }
                size_t rowb = ((size_t)(b_ * HH + hh) * SS + s) * DD;
#pragma unroll
                for (int nt = 0; nt < 8; nt++) {
                    uint32_t hreg, lreg;
                    psplit(vals[nt][0], vals[nt][1], hreg, lreg);
                    *(uint32_t*)&dh[rowb + nt * 8 + c2] = hreg;
                    *(uint32_t*)&dl[rowb + nt * 8 + c2] = lreg;
                }
            }
        }
    }
}

// ---------------------------------------------------------------------------
// Tensor-core causal flash attention (bf16x3 split, mma.sync).
// R7-proven config: CTA = 128 Q rows, 8 warps x 16 rows, 64-wide KV tiles
// double-buffered, uncapped regs. Added: 16-col strip skipping inside
// partial diagonal tiles (skipped strips are provably all-masked -> P=0).
// ---------------------------------------------------------------------------
#define AT_PITCH 144                      // 64 bf16 = 128B data + 16B pad
#define AT_Q (128 * AT_PITCH)             // 18432 per Q tile (hi or lo)
#define AT_KV (64 * AT_PITCH)             // 9216 per K/V tile
#define AT_STAGE (4 * AT_KV)              // Kh,Kl,Vh,Vl = 36864
#define AT_SMEM (2 * AT_Q + 2 * AT_STAGE) // 110592

__global__ __launch_bounds__(256)
void attn_mma(const __nv_bfloat16* __restrict__ qh, const __nv_bfloat16* __restrict__ ql,
              const __nv_bfloat16* __restrict__ kh, const __nv_bfloat16* __restrict__ kl,
              const __nv_bfloat16* __restrict__ vh, const __nv_bfloat16* __restrict__ vl,
              __nv_bfloat16* __restrict__ oh, __nv_bfloat16* __restrict__ ol)
{
    extern __shared__ char smem[];
    const uint32_t sb = smem_u32(smem);
    const int tid = threadIdx.x;
    const int wid = tid >> 5, lane = tid & 31;

    const int mtile = (int)(gridDim.x - 1 - blockIdx.x);   // heavy CTAs first
    const int bh = blockIdx.y;
    const int m0 = mtile * 128;
    const int ntmax = 2 * mtile + 1;
    const size_t hbase = (size_t)bh * SS * DD;
    const __nv_bfloat16* qhp = qh + hbase;
    const __nv_bfloat16* qlp = ql + hbase;
    const __nv_bfloat16* khp = kh + hbase;
    const __nv_bfloat16* klp = kl + hbase;
    const __nv_bfloat16* vhp = vh + hbase;
    const __nv_bfloat16* vlp = vl + hbase;

    // ---- load Q tile (hi+lo) ----
#pragma unroll
    for (int i = 0; i < 4; i++) {
        int cid = tid + i * 256;           // 0..1023
        int row = cid >> 3;
        int j   = cid & 7;
        uint32_t off = (uint32_t)(row * AT_PITCH + j * 16);
        size_t g = (size_t)(m0 + row) * DD + j * 8;
        cp_async16(sb + off, qhp + g);
        cp_async16(sb + AT_Q + off, qlp + g);
    }
    cp_commit();

    auto load_kv = [&](int t) {
        if (t <= ntmax) {
            uint32_t base = sb + 2 * AT_Q + (uint32_t)(t & 1) * AT_STAGE;
            int n0 = t * 64;
#pragma unroll
            for (int i = 0; i < 2; i++) {
                int cid = tid + i * 256;       // 0..511
                int row = cid >> 3;
                int j   = cid & 7;
                uint32_t off = (uint32_t)(row * AT_PITCH + j * 16);
                size_t g = (size_t)(n0 + row) * DD + j * 8;
                cp_async16(base + 0 * AT_KV + off, khp + g);
                cp_async16(base + 1 * AT_KV + off, klp + g);
                cp_async16(base + 2 * AT_KV + off, vhp + g);
                cp_async16(base + 3 * AT_KV + off, vlp + g);
            }
        }
        cp_commit();
    };
    load_kv(0);
    load_kv(1);

    float oacc[8][4];
#pragma unroll
    for (int d = 0; d < 8; d++)
#pragma unroll
        for (int j = 0; j < 4; j++) oacc[d][j] = 0.f;
    float mi0 = -1e30f, mi1 = -1e30f, li0 = 0.f, li1 = 0.f;
    uint32_t qfh[4][4], qfl[4][4];

    const int wr0 = m0 + wid * 16;     // warp's first global Q row

    for (int nt = 0; nt <= ntmax; nt++) {
        cp_wait1();
        __syncthreads();               // stage nt (and Q at nt=0) visible

        if (nt == 0) {                 // load Q fragments once
#pragma unroll
            for (int kc = 0; kc < 4; kc++) {
                uint32_t a = sb + (uint32_t)((wid * 16 + (lane & 15)) * AT_PITCH)
                           + (uint32_t)(kc * 32) + (uint32_t)((lane >> 4) * 16);
                ldsm_x4(qfh[kc], a);
                ldsm_x4(qfl[kc], a + AT_Q);
            }
        }

        const int n0 = nt * 64;
        const int climit = wr0 + 15;   // last valid column for this warp
        if (n0 <= climit) {            // warp has unmasked rows in this tile
            const bool part = (n0 + 63 > wr0);   // partial (diagonal band) tile
            const uint32_t kvb = sb + 2 * AT_Q + (uint32_t)(nt & 1) * AT_STAGE;

            // ---- S = Q K^T (3-term split); skip fully-masked 16-col strips ----
            float sacc[8][4];
#pragma unroll
            for (int t8 = 0; t8 < 8; t8++)
#pragma unroll
                for (int j = 0; j < 4; j++) sacc[t8][j] = 0.f;

#pragma unroll
            for (int kc = 0; kc < 4; kc++) {
                uint32_t colo = (uint32_t)(kc * 32) + (uint32_t)((lane >> 4) * 16);
#pragma unroll
                for (int st = 0; st < 4; st++) {
                    if (!part || n0 + st * 16 <= climit) {
                        uint32_t a = kvb + (uint32_t)((st * 16 + (lane & 15)) * AT_PITCH) + colo;
                        uint32_t k4h[4], k4l[4];
                        ldsm_x4(k4h, a);
                        ldsm_x4(k4l, a + AT_KV);
                        mma16816(sacc[2 * st],     qfh[kc], k4h[0], k4h[2]);
                        mma16816(sacc[2 * st],     qfh[kc], k4l[0], k4l[2]);
                        mma16816(sacc[2 * st],     qfl[kc], k4h[0], k4h[2]);
                        mma16816(sacc[2 * st + 1], qfh[kc], k4h[1], k4h[3]);
                        mma16816(sacc[2 * st + 1], qfh[kc], k4l[1], k4l[3]);
                        mma16816(sacc[2 * st + 1], qfl[kc], k4h[1], k4h[3]);
                    }
                }
            }

            // ---- causal mask (partial tiles only; skipped strips -> -inf) ----
            const int rr0 = wr0 + (lane >> 2);
            if (part) {
#pragma unroll
                for (int t8 = 0; t8 < 8; t8++) {
                    int c0 = n0 + t8 * 8 + 2 * (lane & 3);
                    if (c0     > rr0)     sacc[t8][0] = -1e30f;
                    if (c0 + 1 > rr0)     sacc[t8][1] = -1e30f;
                    if (c0     > rr0 + 8) sacc[t8][2] = -1e30f;
                    if (c0 + 1 > rr0 + 8) sacc[t8][3] = -1e30f;
                }
            }

            // ---- online softmax (rows lane/4 and lane/4+8) ----
            float mx0 = -1e30f, mx1 = -1e30f;
#pragma unroll
            for (int t8 = 0; t8 < 8; t8++) {
                mx0 = fmaxf(mx0, fmaxf(sacc[t8][0], sacc[t8][1]));
                mx1 = fmaxf(mx1, fmaxf(sacc[t8][2], sacc[t8][3]));
            }
            mx0 = fmaxf(mx0, __shfl_xor_sync(0xffffffffu, mx0, 1));
            mx0 = fmaxf(mx0, __shfl_xor_sync(0xffffffffu, mx0, 2));
            mx1 = fmaxf(mx1, __shfl_xor_sync(0xffffffffu, mx1, 1));
            mx1 = fmaxf(mx1, __shfl_xor_sync(0xffffffffu, mx1, 2));
            float mn0 = fmaxf(mi0, mx0), mn1 = fmaxf(mi1, mx1);
            float al0 = __expf(mi0 - mn0), al1 = __expf(mi1 - mn1);
            mi0 = mn0; mi1 = mn1;
            float s0 = 0.f, s1 = 0.f;
#pragma unroll
            for (int t8 = 0; t8 < 8; t8++) {
                float p0 = __expf(sacc[t8][0] - mn0);
                float p1 = __expf(sacc[t8][1] - mn0);
                float p2 = __expf(sacc[t8][2] - mn1);
                float p3 = __expf(sacc[t8][3] - mn1);
                sacc[t8][0] = p0; sacc[t8][1] = p1;
                sacc[t8][2] = p2; sacc[t8][3] = p3;
                s0 += p0 + p1; s1 += p2 + p3;
            }
            li0 = li0 * al0 + s0;        // lane-partial row sums
            li1 = li1 * al1 + s1;
#pragma unroll
            for (int d = 0; d < 8; d++) {
                oacc[d][0] *= al0; oacc[d][1] *= al0;
                oacc[d][2] *= al1; oacc[d][3] *= al1;
            }

            // ---- P -> bf16 hi/lo A-fragments (S-frag layout == A-frag layout) ----
            uint32_t aPh[4][4], aPl[4][4];
#pragma unroll
            for (int kc = 0; kc < 4; kc++) {
                psplit(sacc[2 * kc][0],     sacc[2 * kc][1],     aPh[kc][0], aPl[kc][0]);
                psplit(sacc[2 * kc][2],     sacc[2 * kc][3],     aPh[kc][1], aPl[kc][1]);
                psplit(sacc[2 * kc + 1][0], sacc[2 * kc + 1][1], aPh[kc][2], aPl[kc][2]);
                psplit(sacc[2 * kc + 1][2], sacc[2 * kc + 1][3], aPh[kc][3], aPl[kc][3]);
            }

            // ---- O += P V (3-term split, V via ldmatrix.trans);
            //      skip strips whose P is all-zero (masked) ----
            const uint32_t vbb = kvb + 2 * AT_KV;
#pragma unroll
            for (int kc = 0; kc < 4; kc++) {
                if (!part || n0 + kc * 16 <= climit) {
#pragma unroll
                    for (int vp = 0; vp < 4; vp++) {
                        uint32_t a = vbb + (uint32_t)((kc * 16 + (lane & 15)) * AT_PITCH)
                                   + (uint32_t)(vp * 32) + (uint32_t)((lane >> 4) * 16);
                        uint32_t v4h[4], v4l[4];
                        ldsm_x4_t(v4h, a);
                        ldsm_x4_t(v4l, a + AT_KV);
                        mma16816(oacc[2 * vp],     aPh[kc], v4h[0], v4h[1]);
                        mma16816(oacc[2 * vp],     aPl[kc], v4h[0], v4h[1]);
                        mma16816(oacc[2 * vp],     aPh[kc], v4l[0], v4l[1]);
                        mma16816(oacc[2 * vp + 1], aPh[kc], v4h[2], v4h[3]);
                        mma16816(oacc[2 * vp + 1], aPl[kc], v4h[2], v4h[3]);
                        mma16816(oacc[2 * vp + 1], aPh[kc], v4l[2], v4l[3]);
                    }
                }
            }
        }

        __syncthreads();               // all warps done reading slot nt&1
        load_kv(nt + 2);
    }

    // ---- normalize + write split bf16 output [m][E] at cols h*64.. ----
    li0 += __shfl_xor_sync(0xffffffffu, li0, 1);
    li0 += __shfl_xor_sync(0xffffffffu, li0, 2);
    li1 += __shfl_xor_sync(0xffffffffu, li1, 1);
    li1 += __shfl_xor_sync(0xffffffffu, li1, 2);
    const float inv0 = 1.f / li0, inv1 = 1.f / li1;

    const int b_ = bh / HH, h_ = bh % HH;
    const int r0g = m0 + wid * 16 + (lane >> 2);
#pragma unroll
    for (int dt = 0; dt < 8; dt++) {
        int col = h_ * 64 + dt * 8 + 2 * (lane & 3);
        size_t o0 = (size_t)(b_ * SS + r0g) * EE + col;
        size_t o1 = (size_t)(b_ * SS + r0g + 8) * EE + col;
        uint32_t hreg, lreg;
        psplit(oacc[dt][0] * inv0, oacc[dt][1] * inv0, hreg, lreg);
        *(uint32_t*)&oh[o0] = hreg;
        *(uint32_t*)&ol[o0] = lreg;
        psplit(oacc[dt][2] * inv1, oacc[dt][3] * inv1, hreg, lreg);
        *(uint32_t*)&oh[o1] = hreg;
        *(uint32_t*)&ol[o1] = lreg;
    }
}

// ---------------------------------------------------------------------------
extern "C" void kernel_launch(void* const* d_in, const int* in_sizes, int n_in,
                              void* d_out, int out_size)
{
    (void)in_sizes; (void)n_in; (void)out_size;
    const float* x  = (const float*)d_in[0];
    const float* Wq = (const float*)d_in[1];
    const float* bq = (const float*)d_in[2];
    const float* Wk = (const float*)d_in[3];
    const float* bk = (const float*)d_in[4];
    const float* Wv = (const float*)d_in[5];
    const float* bv = (const float*)d_in[6];
    const float* Wp = (const float*)d_in[7];
    const float* bp = (const float*)d_in[8];

    __nv_bfloat16 *ah, *al, *wth, *wtl, *qh, *ql, *kh, *kl, *vh, *vl;
    cudaGetSymbolAddress((void**)&ah,  g_ah);
    cudaGetSymbolAddress((void**)&al,  g_al);
    cudaGetSymbolAddress((void**)&wth, g_wth);
    cudaGetSymbolAddress((void**)&wtl, g_wtl);
    cudaGetSymbolAddress((void**)&qh,  g_qh);
    cudaGetSymbolAddress((void**)&ql,  g_ql);
    cudaGetSymbolAddress((void**)&kh,  g_kh);
    cudaGetSymbolAddress((void**)&kl,  g_kl);
    cudaGetSymbolAddress((void**)&vh,  g_vh);
    cudaGetSymbolAddress((void**)&vl,  g_vl);

    cudaFuncSetAttribute(gemm_mma<1>,
                         cudaFuncAttributeMaxDynamicSharedMemorySize, GM_SMEM);
    cudaFuncSetAttribute(gemm_mma<0>,
                         cudaFuncAttributeMaxDynamicSharedMemorySize, GM_SMEM);
    cudaFuncSetAttribute(attn_mma,
                         cudaFuncAttributeMaxDynamicSharedMemorySize, AT_SMEM);

    // Split x and all 4 weight matrices into bf16 hi/lo (weights transposed)
    split_convert<<<(MT * EE + 255) / 256, 256>>>(x, ah, al, MT * EE);
    transpose_split<<<dim3(EE / 32, EE / 32, 4), 256>>>(Wq, Wk, Wv, Wp, wth, wtl);

    // Fused Q/K/V projections + bias + RoPE + scale + split -> bf16 [B,H,S,D]
    gemm_mma<1><<<dim3(EE / 128, MT / 128, 3), 256, GM_SMEM>>>(
        ah, al, wth, wtl, bq, bk, bv, nullptr, nullptr,
        qh, ql, kh, kl, vh, vl);

    // Tensor-core causal flash attention -> split bf16 [B,S,E] (into ah/al)
    attn_mma<<<dim3(SS / 128, BB * HH), 256, AT_SMEM>>>(
        qh, ql, kh, kl, vh, vl, ah, al);

    // Output projection -> d_out
    gemm_mma<0><<<dim3(EE / 128, MT / 128, 1), 256, GM_SMEM>>>(
        ah, al, wth, wtl, nullptr, nullptr, nullptr, bp, (float*)d_out,
        nullptr, nullptr, nullptr, nullptr, nullptr, nullptr);
}

// round 13
// speedup vs baseline: 1.3114x; 1.1384x over previous
#include <cuda_runtime.h>
#include <cuda_bf16.h>
#include <cuda_fp16.h>
#include <math.h>
#include <stdint.h>

#define BB 2
#define SS 2048
#define EE 768
#define HH 12
#define DD 64
#define MT (BB*SS)

// ---------------------------------------------------------------------------
// Scratch (allocation-free rule: __device__ globals)
// ---------------------------------------------------------------------------
__device__ __nv_bfloat16 g_ah[(size_t)MT*EE];
__device__ __nv_bfloat16 g_al[(size_t)MT*EE];
__device__ __nv_bfloat16 g_wth[(size_t)4*EE*EE];   // [4][n][k] = W[k][n] hi
__device__ __nv_bfloat16 g_wtl[(size_t)4*EE*EE];   // lo
__device__ __half g_qh[(size_t)BB*HH*SS*DD];       // fp16 q hi
__device__ __half g_ql[(size_t)BB*HH*SS*DD];       // fp16 q lo (residual)
__device__ __half g_kh[(size_t)BB*HH*SS*DD];       // fp16 0.125*k (single)
__device__ __half g_vh[(size_t)BB*HH*SS*DD];       // fp16 v hi
__device__ __half g_vl[(size_t)BB*HH*SS*DD];       // fp16 v lo

// ---------------------------------------------------------------------------
// PTX helpers (BASE ISA ONLY — harness ptxas targets sm_103 without 'a')
// ---------------------------------------------------------------------------
__device__ __forceinline__ uint32_t smem_u32(const void* p) {
    uint32_t a;
    asm("{ .reg .u64 t; cvta.to.shared.u64 t, %1; cvt.u32.u64 %0, t; }"
        : "=r"(a) : "l"(p));
    return a;
}
__device__ __forceinline__ void cp_async16(uint32_t saddr, const void* gaddr) {
    asm volatile("cp.async.cg.shared.global [%0], [%1], 16;"
                 :: "r"(saddr), "l"(gaddr) : "memory");
}
__device__ __forceinline__ void cp_commit() {
    asm volatile("cp.async.commit_group;" ::: "memory");
}
__device__ __forceinline__ void cp_wait1() {
    asm volatile("cp.async.wait_group 1;" ::: "memory");
}
__device__ __forceinline__ void cp_wait0() {
    asm volatile("cp.async.wait_group 0;" ::: "memory");
}
__device__ __forceinline__ void ldsm_x4(uint32_t* r, uint32_t addr) {
    asm volatile("ldmatrix.sync.aligned.m8n8.x4.shared.b16 {%0,%1,%2,%3}, [%4];"
                 : "=r"(r[0]), "=r"(r[1]), "=r"(r[2]), "=r"(r[3]) : "r"(addr));
}
__device__ __forceinline__ void ldsm_x4_t(uint32_t* r, uint32_t addr) {
    asm volatile("ldmatrix.sync.aligned.m8n8.x4.trans.shared.b16 {%0,%1,%2,%3}, [%4];"
                 : "=r"(r[0]), "=r"(r[1]), "=r"(r[2]), "=r"(r[3]) : "r"(addr));
}
// bf16 mma (GEMMs)
__device__ __forceinline__ void mma16816(float* c, const uint32_t* a,
                                         uint32_t b0, uint32_t b1) {
    asm volatile(
        "mma.sync.aligned.m16n8k16.row.col.f32.bf16.bf16.f32 "
        "{%0,%1,%2,%3}, {%4,%5,%6,%7}, {%8,%9}, {%0,%1,%2,%3};"
        : "+f"(c[0]), "+f"(c[1]), "+f"(c[2]), "+f"(c[3])
        : "r"(a[0]), "r"(a[1]), "r"(a[2]), "r"(a[3]), "r"(b0), "r"(b1));
}
// fp16 mma (attention)
__device__ __forceinline__ void mma16816h(float* c, const uint32_t* a,
                                          uint32_t b0, uint32_t b1) {
    asm volatile(
        "mma.sync.aligned.m16n8k16.row.col.f32.f16.f16.f32 "
        "{%0,%1,%2,%3}, {%4,%5,%6,%7}, {%8,%9}, {%0,%1,%2,%3};"
        : "+f"(c[0]), "+f"(c[1]), "+f"(c[2]), "+f"(c[3])
        : "r"(a[0]), "r"(a[1]), "r"(a[2]), "r"(a[3]), "r"(b0), "r"(b1));
}
// bf16 splits (GEMM path)
__device__ __forceinline__ void psplit(float p0, float p1,
                                       uint32_t& hreg, uint32_t& lreg) {
    __nv_bfloat162 hh = __float22bfloat162_rn(make_float2(p0, p1));
    float r0 = p0 - __bfloat162float(hh.x);
    float r1 = p1 - __bfloat162float(hh.y);
    __nv_bfloat162 ll = __float22bfloat162_rn(make_float2(r0, r1));
    hreg = *reinterpret_cast<uint32_t*>(&hh);
    lreg = *reinterpret_cast<uint32_t*>(&ll);
}
__device__ __forceinline__ void fsplit(float x, __nv_bfloat16& h, __nv_bfloat16& l) {
    h = __float2bfloat16(x);
    l = __float2bfloat16(x - __bfloat162float(h));
}
// fp16 split + pack (attention operand path)
__device__ __forceinline__ void hpsplit(float p0, float p1,
                                        uint32_t& hreg, uint32_t& lreg) {
    __half2 hh = __floats2half2_rn(p0, p1);
    float r0 = p0 - __low2float(hh);
    float r1 = p1 - __high2float(hh);
    __half2 ll = __floats2half2_rn(r0, r1);
    hreg = *reinterpret_cast<uint32_t*>(&hh);
    lreg = *reinterpret_cast<uint32_t*>(&ll);
}
__device__ __forceinline__ uint32_t hpack(float p0, float p1) {
    __half2 hh = __floats2half2_rn(p0, p1);
    return *reinterpret_cast<uint32_t*>(&hh);
}

// ---------------------------------------------------------------------------
// Precision-split conversion: x -> (bf16 hi, bf16 lo)
// ---------------------------------------------------------------------------
__global__ __launch_bounds__(256)
void split_convert(const float* __restrict__ in, __nv_bfloat16* __restrict__ h,
                   __nv_bfloat16* __restrict__ l, int n)
{
    int i = blockIdx.x * blockDim.x + threadIdx.x;
    if (i < n) {
        float x = in[i];
        __nv_bfloat16 hi, lo;
        fsplit(x, hi, lo);
        h[i] = hi;
        l[i] = lo;
    }
}

// Transpose + split: Wt[z][n][k] = W_z[k][n]  (hi/lo bf16)
__global__ __launch_bounds__(256)
void transpose_split(const float* __restrict__ W0, const float* __restrict__ W1,
                     const float* __restrict__ W2, const float* __restrict__ W3,
                     __nv_bfloat16* __restrict__ th, __nv_bfloat16* __restrict__ tl)
{
    __shared__ float t[32][33];
    const float* W = (blockIdx.z == 0) ? W0 : (blockIdx.z == 1) ? W1
                   : (blockIdx.z == 2) ? W2 : W3;
    int n0 = blockIdx.x * 32, k0 = blockIdx.y * 32;
    int tx = threadIdx.x & 31, ty = threadIdx.x >> 5;
#pragma unroll
    for (int i = 0; i < 4; i++)
        t[ty + 8 * i][tx] = W[(size_t)(k0 + ty + 8 * i) * EE + n0 + tx];
    __syncthreads();
    size_t base = (size_t)blockIdx.z * EE * EE;
#pragma unroll
    for (int i = 0; i < 4; i++) {
        int row = ty + 8 * i;                 // local n
        float x = t[tx][row];                 // = W[k0+tx][n0+row]
        __nv_bfloat16 hi, lo;
        fsplit(x, hi, lo);
        size_t o = base + (size_t)(n0 + row) * EE + k0 + tx;
        th[o] = hi;
        tl[o] = lo;
    }
}

// ---------------------------------------------------------------------------
// mma.sync GEMM: C[M,768] = A[M,768] @ W[768,768] + bias  (bf16x3 split)
// CTA 128x128, 8 warps of 32x64, K-chunk 32, 2-stage cp.async, occupancy 2.
// MODE 0: fp32 C[m*EE+n] to fout.
// MODE 1: fused epilogue — bias + RoPE (smem trig table) + fp16 outputs:
//         q -> fp16 hi/lo (unscaled), k -> fp16 single (x0.125), v -> hi/lo.
// ---------------------------------------------------------------------------
#define KC 32
#define NCH (EE / KC)                 // 24
#define GM_PITCH 80                   // bytes per 32-bf16 row (padded from 64)
#define GM_TILE (128 * GM_PITCH)      // 10240
#define GM_BUF (4 * GM_TILE)          // Ah, Al, Bh, Bl
#define GM_SMEM (2 * GM_BUF)          // 81920 -> 2 CTAs/SM

template<int MODE>
__global__ __launch_bounds__(256, 2)
void gemm_mma(const __nv_bfloat16* __restrict__ Ah, const __nv_bfloat16* __restrict__ Al,
              const __nv_bfloat16* __restrict__ Wth, const __nv_bfloat16* __restrict__ Wtl,
              const float* b0, const float* b1, const float* b2, const float* b3,
              float* fout,
              __half* qh, __half* ql, __half* kh, __half* vh, __half* vl)
{
    extern __shared__ char smem[];
    const uint32_t sb = smem_u32(smem);
    const int tid = threadIdx.x;
    const int wid = tid >> 5, lane = tid & 31;
    const int wm = wid & 3;          // 4 m-groups of 32 rows
    const int wn = wid >> 2;         // 2 n-groups of 64 cols

    const int wsel = (MODE == 1) ? (int)blockIdx.z : 3;
    const float* bias = (wsel == 0) ? b0 : (wsel == 1) ? b1 : (wsel == 2) ? b2 : b3;
    const __nv_bfloat16* Bh = Wth + (size_t)wsel * EE * EE;
    const __nv_bfloat16* Bl = Wtl + (size_t)wsel * EE * EE;
    const int m0 = blockIdx.y * 128;
    const int n0 = blockIdx.x * 128;

    auto load_chunk = [&](int c) {
        uint32_t buf = sb + (uint32_t)(c & 1) * GM_BUF;
        int k0 = c * KC;
#pragma unroll
        for (int i = 0; i < 2; i++) {
            int idx = tid + i * 256;            // 0..511
            int row = idx >> 2;                 // 0..127
            int j   = idx & 3;                  // 16B quad
            uint32_t off = (uint32_t)(row * GM_PITCH + j * 16);
            size_t ga = (size_t)(m0 + row) * EE + k0 + j * 8;
            size_t gb = (size_t)(n0 + row) * EE + k0 + j * 8;
            cp_async16(buf + 0 * GM_TILE + off, Ah + ga);
            cp_async16(buf + 1 * GM_TILE + off, Al + ga);
            cp_async16(buf + 2 * GM_TILE + off, Bh + gb);
            cp_async16(buf + 3 * GM_TILE + off, Bl + gb);
        }
        cp_commit();
    };

    float acc[2][8][4];
#pragma unroll
    for (int mt = 0; mt < 2; mt++)
#pragma unroll
        for (int nt = 0; nt < 8; nt++)
#pragma unroll
            for (int i = 0; i < 4; i++) acc[mt][nt][i] = 0.f;

    load_chunk(0);
    load_chunk(1);

    const int rA = wm * 32 + (lane & 15);
    const int rB = wn * 64 + (lane & 15);
    const uint32_t chalf = (uint32_t)((lane >> 4) * 16);

    for (int c = 0; c < NCH; c++) {
        cp_wait1();            // chunk c resident
        __syncthreads();
        uint32_t buf = sb + (uint32_t)(c & 1) * GM_BUF;

#pragma unroll
        for (int ks = 0; ks < 2; ks++) {
            uint32_t colo = (uint32_t)(ks * 32) + chalf;
            uint32_t ah[2][4], al[2][4], bh[4][4], bl[4][4];
#pragma unroll
            for (int mt = 0; mt < 2; mt++) {
                uint32_t off = (uint32_t)((rA + mt * 16) * GM_PITCH) + colo;
                ldsm_x4(ah[mt], buf + 0 * GM_TILE + off);
                ldsm_x4(al[mt], buf + 1 * GM_TILE + off);
            }
#pragma unroll
            for (int p = 0; p < 4; p++) {
                uint32_t off = (uint32_t)((rB + p * 16) * GM_PITCH) + colo;
                ldsm_x4(bh[p], buf + 2 * GM_TILE + off);
                ldsm_x4(bl[p], buf + 3 * GM_TILE + off);
            }
#pragma unroll
            for (int mt = 0; mt < 2; mt++)
#pragma unroll
                for (int nt = 0; nt < 8; nt++) {
                    const int p = nt >> 1, q = nt & 1;
                    mma16816(acc[mt][nt], ah[mt], bh[p][q], bh[p][q + 2]);
                    mma16816(acc[mt][nt], ah[mt], bl[p][q], bl[p][q + 2]);
                    mma16816(acc[mt][nt], al[mt], bh[p][q], bh[p][q + 2]);
                }
        }

        __syncthreads();       // all warps done reading slot c&1
        if (c + 2 < NCH) load_chunk(c + 2);
        else cp_commit();
    }

    if (MODE == 0) {
        // plain fp32 epilogue (output projection -> d_out)
        const int mrow0 = m0 + wm * 32;
#pragma unroll
        for (int mt = 0; mt < 2; mt++) {
#pragma unroll
            for (int nt = 0; nt < 8; nt++) {
                int gn = n0 + wn * 64 + nt * 8 + 2 * (lane & 3);
                float2 bv = *(const float2*)&bias[gn];
                int r0 = mrow0 + mt * 16 + (lane >> 2);
                float2 v0 = { acc[mt][nt][0] + bv.x, acc[mt][nt][1] + bv.y };
                float2 v1 = { acc[mt][nt][2] + bv.x, acc[mt][nt][3] + bv.y };
                *(float2*)&fout[(size_t)r0 * EE + gn] = v0;
                *(float2*)&fout[(size_t)(r0 + 8) * EE + gn] = v1;
            }
        }
    } else {
        // fused bias + RoPE + fp16 pack epilogue
        __half *dh, *dl;
        if (wsel == 0)      { dh = qh; dl = ql; }
        else if (wsel == 1) { dh = kh; dl = nullptr; }
        else                { dh = vh; dl = vl; }
        const int hh = (int)blockIdx.x * 2 + wn;     // head index
        const int c2 = 2 * (lane & 3);
        const float RC = 0.28782313662425572f;       // ln(10000)/32

        float2* tab = (float2*)smem;                 // reuse dead stage buffers
        if (wsel < 2) {
            cp_wait0();
            __syncthreads();                         // stage buffers now dead
            for (int idx = tid; idx < 128 * 32; idx += 256) {
                int rl = idx >> 5, i = idx & 31;
                int s = (m0 + rl) & (SS - 1);
                float ang = (float)s * expf(-(float)i * RC);
                float sn, cs;
                sincosf(ang, &sn, &cs);
                tab[idx] = make_float2(cs, sn);
            }
            __syncthreads();
        }

#pragma unroll
        for (int mt = 0; mt < 2; mt++) {
#pragma unroll
            for (int rr = 0; rr < 2; rr++) {
                int rloc = wm * 32 + mt * 16 + (lane >> 2) + rr * 8;
                int r = m0 + rloc;
                int b_ = r >> 11, s = r & (SS - 1);
                float vals[8][2];
#pragma unroll
                for (int nt = 0; nt < 8; nt++) {
                    float2 bv = *(const float2*)&bias[hh * 64 + nt * 8 + c2];
                    vals[nt][0] = acc[mt][nt][2 * rr]     + bv.x;
                    vals[nt][1] = acc[mt][nt][2 * rr + 1] + bv.y;
                }
                if (wsel < 2) {
#pragma unroll
                    for (int nt = 0; nt < 4; nt++) {
#pragma unroll
                        for (int cc = 0; cc < 2; cc++) {
                            int i = nt * 8 + c2 + cc;
                            float2 cs = tab[rloc * 32 + i];
                            float x = vals[nt][cc], y = vals[nt + 4][cc];
                            vals[nt][cc]     = x * cs.x - y * cs.y;
                            vals[nt + 4][cc] = y * cs.x + x * cs.y;
                        }
                    }
                    if (wsel == 1) {                 // fold 1/sqrt(D) into K
#pragma unroll
                        for (int nt = 0; nt < 8; nt++) {
                            vals[nt][0] *= 0.125f;
                            vals[nt][1] *= 0.125f;
                        }
                    }
                }
                size_t rowb = ((size_t)(b_ * HH + hh) * SS + s) * DD;
                if (wsel == 1) {                     // k: single fp16
#pragma unroll
                    for (int nt = 0; nt < 8; nt++)
                        *(uint32_t*)&dh[rowb + nt * 8 + c2] =
                            hpack(vals[nt][0], vals[nt][1]);
                } else {                             // q/v: fp16 hi + lo
#pragma unroll
                    for (int nt = 0; nt < 8; nt++) {
                        uint32_t hreg, lreg;
                        hpsplit(vals[nt][0], vals[nt][1], hreg, lreg);
                        *(uint32_t*)&dh[rowb + nt * 8 + c2] = hreg;
                        *(uint32_t*)&dl[rowb + nt * 8 + c2] = lreg;
                    }
                }
            }
        }
    }
}

// ---------------------------------------------------------------------------
// Tensor-core causal flash attention — fp16 path.
// S = (Qh+Ql)·Kh  (Kh = fp16(0.125*k), only error = K rounding ~5e-4)
// O += Ph·(Vh+Vl) (P single fp16; no psplit)
// CTA = 128 Q rows, 8 warps x 16 rows, 64-wide KV tiles double-buffered,
// per-warp tile skip + 16-col strip skip on partial diagonal tiles.
// ---------------------------------------------------------------------------
#define AT_PITCH 144                      // 64 halves = 128B data + 16B pad
#define AT_Q (128 * AT_PITCH)             // 18432 per Q tile (hi or lo)
#define AT_KV (64 * AT_PITCH)             // 9216 per K/V tile
#define AT_STAGE (3 * AT_KV)              // Kh, Vh, Vl = 27648
#define AT_SMEM (2 * AT_Q + 2 * AT_STAGE) // 92160

__global__ __launch_bounds__(256)
void attn_mma(const __half* __restrict__ qh, const __half* __restrict__ ql,
              const __half* __restrict__ kh,
              const __half* __restrict__ vh, const __half* __restrict__ vl,
              __nv_bfloat16* __restrict__ oh, __nv_bfloat16* __restrict__ ol)
{
    extern __shared__ char smem[];
    const uint32_t sb = smem_u32(smem);
    const int tid = threadIdx.x;
    const int wid = tid >> 5, lane = tid & 31;

    const int mtile = (int)(gridDim.x - 1 - blockIdx.x);   // heavy CTAs first
    const int bh = blockIdx.y;
    const int m0 = mtile * 128;
    const int ntmax = 2 * mtile + 1;
    const size_t hbase = (size_t)bh * SS * DD;
    const __half* qhp = qh + hbase;
    const __half* qlp = ql + hbase;
    const __half* khp = kh + hbase;
    const __half* vhp = vh + hbase;
    const __half* vlp = vl + hbase;

    // ---- load Q tile (hi+lo) ----
#pragma unroll
    for (int i = 0; i < 4; i++) {
        int cid = tid + i * 256;           // 0..1023
        int row = cid >> 3;
        int j   = cid & 7;
        uint32_t off = (uint32_t)(row * AT_PITCH + j * 16);
        size_t g = (size_t)(m0 + row) * DD + j * 8;
        cp_async16(sb + off, qhp + g);
        cp_async16(sb + AT_Q + off, qlp + g);
    }
    cp_commit();

    auto load_kv = [&](int t) {
        if (t <= ntmax) {
            uint32_t base = sb + 2 * AT_Q + (uint32_t)(t & 1) * AT_STAGE;
            int n0 = t * 64;
#pragma unroll
            for (int i = 0; i < 2; i++) {
                int cid = tid + i * 256;       // 0..511
                int row = cid >> 3;
                int j   = cid & 7;
                uint32_t off = (uint32_t)(row * AT_PITCH + j * 16);
                size_t g = (size_t)(n0 + row) * DD + j * 8;
                cp_async16(base + 0 * AT_KV + off, khp + g);
                cp_async16(base + 1 * AT_KV + off, vhp + g);
                cp_async16(base + 2 * AT_KV + off, vlp + g);
            }
        }
        cp_commit();
    };
    load_kv(0);
    load_kv(1);

    float oacc[8][4];
#pragma unroll
    for (int d = 0; d < 8; d++)
#pragma unroll
        for (int j = 0; j < 4; j++) oacc[d][j] = 0.f;
    float mi0 = -1e30f, mi1 = -1e30f, li0 = 0.f, li1 = 0.f;
    uint32_t qfh[4][4], qfl[4][4];

    const int wr0 = m0 + wid * 16;     // warp's first global Q row

    for (int nt = 0; nt <= ntmax; nt++) {
        cp_wait1();
        __syncthreads();               // stage nt (and Q at nt=0) visible

        if (nt == 0) {                 // load Q fragments once
#pragma unroll
            for (int kc = 0; kc < 4; kc++) {
                uint32_t a = sb + (uint32_t)((wid * 16 + (lane & 15)) * AT_PITCH)
                           + (uint32_t)(kc * 32) + (uint32_t)((lane >> 4) * 16);
                ldsm_x4(qfh[kc], a);
                ldsm_x4(qfl[kc], a + AT_Q);
            }
        }

        const int n0 = nt * 64;
        const int climit = wr0 + 15;   // last valid column for this warp
        if (n0 <= climit) {            // warp has unmasked rows in this tile
            const bool part = (n0 + 63 > wr0);   // partial (diagonal band) tile
            const uint32_t kvb = sb + 2 * AT_Q + (uint32_t)(nt & 1) * AT_STAGE;

            // ---- S = (Qh+Ql) Kh; skip fully-masked 16-col strips ----
            float sacc[8][4];
#pragma unroll
            for (int t8 = 0; t8 < 8; t8++)
#pragma unroll
                for (int j = 0; j < 4; j++) sacc[t8][j] = 0.f;

#pragma unroll
            for (int kc = 0; kc < 4; kc++) {
                uint32_t colo = (uint32_t)(kc * 32) + (uint32_t)((lane >> 4) * 16);
#pragma unroll
                for (int st = 0; st < 4; st++) {
                    if (!part || n0 + st * 16 <= climit) {
                        uint32_t a = kvb + (uint32_t)((st * 16 + (lane & 15)) * AT_PITCH) + colo;
                        uint32_t k4[4];
                        ldsm_x4(k4, a);
                        mma16816h(sacc[2 * st],     qfh[kc], k4[0], k4[2]);
                        mma16816h(sacc[2 * st],     qfl[kc], k4[0], k4[2]);
                        mma16816h(sacc[2 * st + 1], qfh[kc], k4[1], k4[3]);
                        mma16816h(sacc[2 * st + 1], qfl[kc], k4[1], k4[3]);
                    }
                }
            }

            // ---- causal mask (partial tiles only; skipped strips -> -inf) ----
            const int rr0 = wr0 + (lane >> 2);
            if (part) {
#pragma unroll
                for (int t8 = 0; t8 < 8; t8++) {
                    int c0 = n0 + t8 * 8 + 2 * (lane & 3);
                    if (c0     > rr0)     sacc[t8][0] = -1e30f;
                    if (c0 + 1 > rr0)     sacc[t8][1] = -1e30f;
                    if (c0     > rr0 + 8) sacc[t8][2] = -1e30f;
                    if (c0 + 1 > rr0 + 8) sacc[t8][3] = -1e30f;
                }
            }

            // ---- online softmax (rows lane/4 and lane/4+8) ----
            float mx0 = -1e30f, mx1 = -1e30f;
#pragma unroll
            for (int t8 = 0; t8 < 8; t8++) {
                mx0 = fmaxf(mx0, fmaxf(sacc[t8][0], sacc[t8][1]));
                mx1 = fmaxf(mx1, fmaxf(sacc[t8][2], sacc[t8][3]));
            }
            mx0 = fmaxf(mx0, __shfl_xor_sync(0xffffffffu, mx0, 1));
            mx0 = fmaxf(mx0, __shfl_xor_sync(0xffffffffu, mx0, 2));
            mx1 = fmaxf(mx1, __shfl_xor_sync(0xffffffffu, mx1, 1));
            mx1 = fmaxf(mx1, __shfl_xor_sync(0xffffffffu, mx1, 2));
            float mn0 = fmaxf(mi0, mx0), mn1 = fmaxf(mi1, mx1);
            float al0 = __expf(mi0 - mn0), al1 = __expf(mi1 - mn1);
            mi0 = mn0; mi1 = mn1;
            float s0 = 0.f, s1 = 0.f;
#pragma unroll
            for (int t8 = 0; t8 < 8; t8++) {
                float p0 = __expf(sacc[t8][0] - mn0);
                float p1 = __expf(sacc[t8][1] - mn0);
                float p2 = __expf(sacc[t8][2] - mn1);
                float p3 = __expf(sacc[t8][3] - mn1);
                sacc[t8][0] = p0; sacc[t8][1] = p1;
                sacc[t8][2] = p2; sacc[t8][3] = p3;
                s0 += p0 + p1; s1 += p2 + p3;
            }
            li0 = li0 * al0 + s0;        // lane-partial row sums
            li1 = li1 * al1 + s1;
#pragma unroll
            for (int d = 0; d < 8; d++) {
                oacc[d][0] *= al0; oacc[d][1] *= al0;
                oacc[d][2] *= al1; oacc[d][3] *= al1;
            }

            // ---- P -> single fp16 A-fragments (no split) ----
            uint32_t aP[4][4];
#pragma unroll
            for (int kc = 0; kc < 4; kc++) {
                aP[kc][0] = hpack(sacc[2 * kc][0],     sacc[2 * kc][1]);
                aP[kc][1] = hpack(sacc[2 * kc][2],     sacc[2 * kc][3]);
                aP[kc][2] = hpack(sacc[2 * kc + 1][0], sacc[2 * kc + 1][1]);
                aP[kc][3] = hpack(sacc[2 * kc + 1][2], sacc[2 * kc + 1][3]);
            }

            // ---- O += Ph (Vh + Vl); skip all-masked strips ----
            const uint32_t vhb = kvb + 1 * AT_KV;
            const uint32_t vlb = kvb + 2 * AT_KV;
#pragma unroll
            for (int kc = 0; kc < 4; kc++) {
                if (!part || n0 + kc * 16 <= climit) {
#pragma unroll
                    for (int vp = 0; vp < 4; vp++) {
                        uint32_t off = (uint32_t)((kc * 16 + (lane & 15)) * AT_PITCH)
                                     + (uint32_t)(vp * 32) + (uint32_t)((lane >> 4) * 16);
                        uint32_t v4h[4], v4l[4];
                        ldsm_x4_t(v4h, vhb + off);
                        ldsm_x4_t(v4l, vlb + off);
                        mma16816h(oacc[2 * vp],     aP[kc], v4h[0], v4h[1]);
                        mma16816h(oacc[2 * vp],     aP[kc], v4l[0], v4l[1]);
                        mma16816h(oacc[2 * vp + 1], aP[kc], v4h[2], v4h[3]);
                        mma16816h(oacc[2 * vp + 1], aP[kc], v4l[2], v4l[3]);
                    }
                }
            }
        }

        __syncthreads();               // all warps done reading slot nt&1
        load_kv(nt + 2);
    }

    // ---- normalize + write split bf16 output [m][E] at cols h*64.. ----
    li0 += __shfl_xor_sync(0xffffffffu, li0, 1);
    li0 += __shfl_xor_sync(0xffffffffu, li0, 2);
    li1 += __shfl_xor_sync(0xffffffffu, li1, 1);
    li1 += __shfl_xor_sync(0xffffffffu, li1, 2);
    const float inv0 = 1.f / li0, inv1 = 1.f / li1;

    const int b_ = bh / HH, h_ = bh % HH;
    const int r0g = m0 + wid * 16 + (lane >> 2);
#pragma unroll
    for (int dt = 0; dt < 8; dt++) {
        int col = h_ * 64 + dt * 8 + 2 * (lane & 3);
        size_t o0 = (size_t)(b_ * SS + r0g) * EE + col;
        size_t o1 = (size_t)(b_ * SS + r0g + 8) * EE + col;
        uint32_t hreg, lreg;
        psplit(oacc[dt][0] * inv0, oacc[dt][1] * inv0, hreg, lreg);
        *(uint32_t*)&oh[o0] = hreg;
        *(uint32_t*)&ol[o0] = lreg;
        psplit(oacc[dt][2] * inv1, oacc[dt][3] * inv1, hreg, lreg);
        *(uint32_t*)&oh[o1] = hreg;
        *(uint32_t*)&ol[o1] = lreg;
    }
}

// ---------------------------------------------------------------------------
extern "C" void kernel_launch(void* const* d_in, const int* in_sizes, int n_in,
                              void* d_out, int out_size)
{
    (void)in_sizes; (void)n_in; (void)out_size;
    const float* x  = (const float*)d_in[0];
    const float* Wq = (const float*)d_in[1];
    const float* bq = (const float*)d_in[2];
    const float* Wk = (const float*)d_in[3];
    const float* bk = (const float*)d_in[4];
    const float* Wv = (const float*)d_in[5];
    const float* bv = (const float*)d_in[6];
    const float* Wp = (const float*)d_in[7];
    const float* bp = (const float*)d_in[8];

    __nv_bfloat16 *ah, *al, *wth, *wtl;
    __half *qh, *ql, *kh, *vh, *vl;
    cudaGetSymbolAddress((void**)&ah,  g_ah);
    cudaGetSymbolAddress((void**)&al,  g_al);
    cudaGetSymbolAddress((void**)&wth, g_wth);
    cudaGetSymbolAddress((void**)&wtl, g_wtl);
    cudaGetSymbolAddress((void**)&qh,  g_qh);
    cudaGetSymbolAddress((void**)&ql,  g_ql);
    cudaGetSymbolAddress((void**)&kh,  g_kh);
    cudaGetSymbolAddress((void**)&vh,  g_vh);
    cudaGetSymbolAddress((void**)&vl,  g_vl);

    cudaFuncSetAttribute(gemm_mma<1>,
                         cudaFuncAttributeMaxDynamicSharedMemorySize, GM_SMEM);
    cudaFuncSetAttribute(gemm_mma<0>,
                         cudaFuncAttributeMaxDynamicSharedMemorySize, GM_SMEM);
    cudaFuncSetAttribute(attn_mma,
                         cudaFuncAttributeMaxDynamicSharedMemorySize, AT_SMEM);

    // Split x and all 4 weight matrices into bf16 hi/lo (weights transposed)
    split_convert<<<(MT * EE + 255) / 256, 256>>>(x, ah, al, MT * EE);
    transpose_split<<<dim3(EE / 32, EE / 32, 4), 256>>>(Wq, Wk, Wv, Wp, wth, wtl);

    // Fused Q/K/V projections + bias + RoPE + fp16 pack -> [B,H,S,D]
    gemm_mma<1><<<dim3(EE / 128, MT / 128, 3), 256, GM_SMEM>>>(
        ah, al, wth, wtl, bq, bk, bv, nullptr, nullptr,
        qh, ql, kh, vh, vl);

    // fp16 tensor-core causal flash attention -> split bf16 [B,S,E] (ah/al)
    attn_mma<<<dim3(SS / 128, BB * HH), 256, AT_SMEM>>>(
        qh, ql, kh, vh, vl, ah, al);

    // Output projection -> d_out
    gemm_mma<0><<<dim3(EE / 128, MT / 128, 1), 256, GM_SMEM>>>(
        ah, al, wth, wtl, nullptr, nullptr, nullptr, bp, (float*)d_out,
        nullptr, nullptr, nullptr, nullptr, nullptr);
}

// round 14
// speedup vs baseline: 1.5610x; 1.1903x over previous
#include <cuda_runtime.h>
#include <cuda_bf16.h>
#include <cuda_fp16.h>
#include <math.h>
#include <stdint.h>

#define BB 2
#define SS 2048
#define EE 768
#define HH 12
#define DD 64
#define MT (BB*SS)

// ---------------------------------------------------------------------------
// Scratch (allocation-free rule: __device__ globals)
// ---------------------------------------------------------------------------
__device__ __half g_ah[(size_t)MT*EE];             // GEMM A hi (x, then attn out)
__device__ __half g_al[(size_t)MT*EE];             // GEMM A lo
__device__ __half g_wt[(size_t)4*EE*EE];           // [4][n][k] = W[k][n], fp16
__device__ __half g_qh[(size_t)BB*HH*SS*DD];       // fp16 q hi
__device__ __half g_ql[(size_t)BB*HH*SS*DD];       // fp16 q lo (residual)
__device__ __half g_kh[(size_t)BB*HH*SS*DD];       // fp16 0.125*k (single)
__device__ __half g_vh[(size_t)BB*HH*SS*DD];       // fp16 v hi
__device__ __half g_vl[(size_t)BB*HH*SS*DD];       // fp16 v lo

// ---------------------------------------------------------------------------
// PTX helpers (BASE ISA ONLY — harness ptxas targets sm_103 without 'a')
// ---------------------------------------------------------------------------
__device__ __forceinline__ uint32_t smem_u32(const void* p) {
    uint32_t a;
    asm("{ .reg .u64 t; cvta.to.shared.u64 t, %1; cvt.u32.u64 %0, t; }"
        : "=r"(a) : "l"(p));
    return a;
}
__device__ __forceinline__ void cp_async16(uint32_t saddr, const void* gaddr) {
    asm volatile("cp.async.cg.shared.global [%0], [%1], 16;"
                 :: "r"(saddr), "l"(gaddr) : "memory");
}
__device__ __forceinline__ void cp_commit() {
    asm volatile("cp.async.commit_group;" ::: "memory");
}
__device__ __forceinline__ void cp_wait1() {
    asm volatile("cp.async.wait_group 1;" ::: "memory");
}
__device__ __forceinline__ void cp_wait0() {
    asm volatile("cp.async.wait_group 0;" ::: "memory");
}
__device__ __forceinline__ void ldsm_x4(uint32_t* r, uint32_t addr) {
    asm volatile("ldmatrix.sync.aligned.m8n8.x4.shared.b16 {%0,%1,%2,%3}, [%4];"
                 : "=r"(r[0]), "=r"(r[1]), "=r"(r[2]), "=r"(r[3]) : "r"(addr));
}
__device__ __forceinline__ void ldsm_x4_t(uint32_t* r, uint32_t addr) {
    asm volatile("ldmatrix.sync.aligned.m8n8.x4.trans.shared.b16 {%0,%1,%2,%3}, [%4];"
                 : "=r"(r[0]), "=r"(r[1]), "=r"(r[2]), "=r"(r[3]) : "r"(addr));
}
// fp16 mma
__device__ __forceinline__ void mma16816h(float* c, const uint32_t* a,
                                          uint32_t b0, uint32_t b1) {
    asm volatile(
        "mma.sync.aligned.m16n8k16.row.col.f32.f16.f16.f32 "
        "{%0,%1,%2,%3}, {%4,%5,%6,%7}, {%8,%9}, {%0,%1,%2,%3};"
        : "+f"(c[0]), "+f"(c[1]), "+f"(c[2]), "+f"(c[3])
        : "r"(a[0]), "r"(a[1]), "r"(a[2]), "r"(a[3]), "r"(b0), "r"(b1));
}
// fp16 split + pack
__device__ __forceinline__ void hpsplit(float p0, float p1,
                                        uint32_t& hreg, uint32_t& lreg) {
    __half2 hh = __floats2half2_rn(p0, p1);
    float r0 = p0 - __low2float(hh);
    float r1 = p1 - __high2float(hh);
    __half2 ll = __floats2half2_rn(r0, r1);
    hreg = *reinterpret_cast<uint32_t*>(&hh);
    lreg = *reinterpret_cast<uint32_t*>(&ll);
}
__device__ __forceinline__ uint32_t hpack(float p0, float p1) {
    __half2 hh = __floats2half2_rn(p0, p1);
    return *reinterpret_cast<uint32_t*>(&hh);
}
__device__ __forceinline__ void hsplit(float x, __half& h, __half& l) {
    h = __float2half_rn(x);
    l = __float2half_rn(x - __half2float(h));
}

// ---------------------------------------------------------------------------
// Precision-split conversion: x -> (fp16 hi, fp16 lo)
// ---------------------------------------------------------------------------
__global__ __launch_bounds__(256)
void split_convert(const float* __restrict__ in, __half* __restrict__ h,
                   __half* __restrict__ l, int n)
{
    int i = blockIdx.x * blockDim.x + threadIdx.x;
    if (i < n) {
        __half hi, lo;
        hsplit(in[i], hi, lo);
        h[i] = hi;
        l[i] = lo;
    }
}

// Transpose: Wt[z][n][k] = W_z[k][n]  (single fp16)
__global__ __launch_bounds__(256)
void transpose_w(const float* __restrict__ W0, const float* __restrict__ W1,
                 const float* __restrict__ W2, const float* __restrict__ W3,
                 __half* __restrict__ th)
{
    __shared__ float t[32][33];
    const float* W = (blockIdx.z == 0) ? W0 : (blockIdx.z == 1) ? W1
                   : (blockIdx.z == 2) ? W2 : W3;
    int n0 = blockIdx.x * 32, k0 = blockIdx.y * 32;
    int tx = threadIdx.x & 31, ty = threadIdx.x >> 5;
#pragma unroll
    for (int i = 0; i < 4; i++)
        t[ty + 8 * i][tx] = W[(size_t)(k0 + ty + 8 * i) * EE + n0 + tx];
    __syncthreads();
    size_t base = (size_t)blockIdx.z * EE * EE;
#pragma unroll
    for (int i = 0; i < 4; i++) {
        int row = ty + 8 * i;                 // local n
        th[base + (size_t)(n0 + row) * EE + k0 + tx] = __float2half_rn(t[tx][row]);
    }
}

// ---------------------------------------------------------------------------
// fp16 mma.sync GEMM: C = A @ W + bias.  A = fp16 hi+lo (exact to 2^-22),
// W = single fp16 (error = W rounding ~2^-12).  2 MMAs per k-step (was 3).
// CTA 128x128, 8 warps of 32x64, K-chunk 32, 2-stage cp.async, occupancy 2.
// MODE 0: fp32 C[m*EE+n] to fout.
// MODE 1: fused epilogue — bias + RoPE (smem trig table) + fp16 outputs:
//         q -> fp16 hi/lo (unscaled), k -> fp16 single (x0.125), v -> hi/lo.
// ---------------------------------------------------------------------------
#define KC 32
#define NCH (EE / KC)                 // 24
#define GM_PITCH 80                   // bytes per 32-half row (padded from 64)
#define GM_TILE (128 * GM_PITCH)      // 10240
#define GM_BUF (3 * GM_TILE)          // Ah, Al, B = 30720
#define GM_SMEM (2 * GM_BUF)          // 61440 -> 2 CTAs/SM

template<int MODE>
__global__ __launch_bounds__(256, 2)
void gemm_mma(const __half* __restrict__ Ah, const __half* __restrict__ Al,
              const __half* __restrict__ Wt,
              const float* b0, const float* b1, const float* b2, const float* b3,
              float* fout,
              __half* qh, __half* ql, __half* kh, __half* vh, __half* vl)
{
    extern __shared__ char smem[];
    const uint32_t sb = smem_u32(smem);
    const int tid = threadIdx.x;
    const int wid = tid >> 5, lane = tid & 31;
    const int wm = wid & 3;          // 4 m-groups of 32 rows
    const int wn = wid >> 2;         // 2 n-groups of 64 cols

    const int wsel = (MODE == 1) ? (int)blockIdx.z : 3;
    const float* bias = (wsel == 0) ? b0 : (wsel == 1) ? b1 : (wsel == 2) ? b2 : b3;
    const __half* Bw = Wt + (size_t)wsel * EE * EE;
    const int m0 = blockIdx.y * 128;
    const int n0 = blockIdx.x * 128;

    auto load_chunk = [&](int c) {
        uint32_t buf = sb + (uint32_t)(c & 1) * GM_BUF;
        int k0 = c * KC;
#pragma unroll
        for (int i = 0; i < 2; i++) {
            int idx = tid + i * 256;            // 0..511
            int row = idx >> 2;                 // 0..127
            int j   = idx & 3;                  // 16B quad
            uint32_t off = (uint32_t)(row * GM_PITCH + j * 16);
            size_t ga = (size_t)(m0 + row) * EE + k0 + j * 8;
            size_t gb = (size_t)(n0 + row) * EE + k0 + j * 8;
            cp_async16(buf + 0 * GM_TILE + off, Ah + ga);
            cp_async16(buf + 1 * GM_TILE + off, Al + ga);
            cp_async16(buf + 2 * GM_TILE + off, Bw + gb);
        }
        cp_commit();
    };

    float acc[2][8][4];
#pragma unroll
    for (int mt = 0; mt < 2; mt++)
#pragma unroll
        for (int nt = 0; nt < 8; nt++)
#pragma unroll
            for (int i = 0; i < 4; i++) acc[mt][nt][i] = 0.f;

    load_chunk(0);
    load_chunk(1);

    const int rA = wm * 32 + (lane & 15);
    const int rB = wn * 64 + (lane & 15);
    const uint32_t chalf = (uint32_t)((lane >> 4) * 16);

    for (int c = 0; c < NCH; c++) {
        cp_wait1();            // chunk c resident
        __syncthreads();
        uint32_t buf = sb + (uint32_t)(c & 1) * GM_BUF;

#pragma unroll
        for (int ks = 0; ks < 2; ks++) {
            uint32_t colo = (uint32_t)(ks * 32) + chalf;
            uint32_t ah[2][4], al[2][4], bw[4][4];
#pragma unroll
            for (int mt = 0; mt < 2; mt++) {
                uint32_t off = (uint32_t)((rA + mt * 16) * GM_PITCH) + colo;
                ldsm_x4(ah[mt], buf + 0 * GM_TILE + off);
                ldsm_x4(al[mt], buf + 1 * GM_TILE + off);
            }
#pragma unroll
            for (int p = 0; p < 4; p++) {
                uint32_t off = (uint32_t)((rB + p * 16) * GM_PITCH) + colo;
                ldsm_x4(bw[p], buf + 2 * GM_TILE + off);
            }
#pragma unroll
            for (int mt = 0; mt < 2; mt++)
#pragma unroll
                for (int nt = 0; nt < 8; nt++) {
                    const int p = nt >> 1, q = nt & 1;
                    mma16816h(acc[mt][nt], ah[mt], bw[p][q], bw[p][q + 2]);
                    mma16816h(acc[mt][nt], al[mt], bw[p][q], bw[p][q + 2]);
                }
        }

        __syncthreads();       // all warps done reading slot c&1
        if (c + 2 < NCH) load_chunk(c + 2);
        else cp_commit();
    }

    if (MODE == 0) {
        // plain fp32 epilogue (output projection -> d_out)
        const int mrow0 = m0 + wm * 32;
#pragma unroll
        for (int mt = 0; mt < 2; mt++) {
#pragma unroll
            for (int nt = 0; nt < 8; nt++) {
                int gn = n0 + wn * 64 + nt * 8 + 2 * (lane & 3);
                float2 bv = *(const float2*)&bias[gn];
                int r0 = mrow0 + mt * 16 + (lane >> 2);
                float2 v0 = { acc[mt][nt][0] + bv.x, acc[mt][nt][1] + bv.y };
                float2 v1 = { acc[mt][nt][2] + bv.x, acc[mt][nt][3] + bv.y };
                *(float2*)&fout[(size_t)r0 * EE + gn] = v0;
                *(float2*)&fout[(size_t)(r0 + 8) * EE + gn] = v1;
            }
        }
    } else {
        // fused bias + RoPE + fp16 pack epilogue
        __half *dh, *dl;
        if (wsel == 0)      { dh = qh; dl = ql; }
        else if (wsel == 1) { dh = kh; dl = nullptr; }
        else                { dh = vh; dl = vl; }
        const int hh = (int)blockIdx.x * 2 + wn;     // head index
        const int c2 = 2 * (lane & 3);
        const float RC = 0.28782313662425572f;       // ln(10000)/32

        float2* tab = (float2*)smem;                 // reuse dead stage buffers
        if (wsel < 2) {
            cp_wait0();
            __syncthreads();                         // stage buffers now dead
            for (int idx = tid; idx < 128 * 32; idx += 256) {
                int rl = idx >> 5, i = idx & 31;
                int s = (m0 + rl) & (SS - 1);
                float ang = (float)s * expf(-(float)i * RC);
                float sn, cs;
                sincosf(ang, &sn, &cs);
                tab[idx] = make_float2(cs, sn);
            }
            __syncthreads();
        }

#pragma unroll
        for (int mt = 0; mt < 2; mt++) {
#pragma unroll
            for (int rr = 0; rr < 2; rr++) {
                int rloc = wm * 32 + mt * 16 + (lane >> 2) + rr * 8;
                int r = m0 + rloc;
                int b_ = r >> 11, s = r & (SS - 1);
                float vals[8][2];
#pragma unroll
                for (int nt = 0; nt < 8; nt++) {
                    float2 bv = *(const float2*)&bias[hh * 64 + nt * 8 + c2];
                    vals[nt][0] = acc[mt][nt][2 * rr]     + bv.x;
                    vals[nt][1] = acc[mt][nt][2 * rr + 1] + bv.y;
                }
                if (wsel < 2) {
#pragma unroll
                    for (int nt = 0; nt < 4; nt++) {
#pragma unroll
                        for (int cc = 0; cc < 2; cc++) {
                            int i = nt * 8 + c2 + cc;
                            float2 cs = tab[rloc * 32 + i];
                            float x = vals[nt][cc], y = vals[nt + 4][cc];
                            vals[nt][cc]     = x * cs.x - y * cs.y;
                            vals[nt + 4][cc] = y * cs.x + x * cs.y;
                        }
                    }
                    if (wsel == 1) {                 // fold 1/sqrt(D) into K
#pragma unroll
                        for (int nt = 0; nt < 8; nt++) {
                            vals[nt][0] *= 0.125f;
                            vals[nt][1] *= 0.125f;
                        }
                    }
                }
                size_t rowb = ((size_t)(b_ * HH + hh) * SS + s) * DD;
                if (wsel == 1) {                     // k: single fp16
#pragma unroll
                    for (int nt = 0; nt < 8; nt++)
                        *(uint32_t*)&dh[rowb + nt * 8 + c2] =
                            hpack(vals[nt][0], vals[nt][1]);
                } else {                             // q/v: fp16 hi + lo
#pragma unroll
                    for (int nt = 0; nt < 8; nt++) {
                        uint32_t hreg, lreg;
                        hpsplit(vals[nt][0], vals[nt][1], hreg, lreg);
                        *(uint32_t*)&dh[rowb + nt * 8 + c2] = hreg;
                        *(uint32_t*)&dl[rowb + nt * 8 + c2] = lreg;
                    }
                }
            }
        }
    }
}

// ---------------------------------------------------------------------------
// Tensor-core causal flash attention — fp16 path (R13-proven).
// S = (Qh+Ql)·Kh ; O += Ph·(Vh+Vl).  Output now fp16 hi/lo (feeds fp16 GEMM).
// ---------------------------------------------------------------------------
#define AT_PITCH 144                      // 64 halves = 128B data + 16B pad
#define AT_Q (128 * AT_PITCH)             // 18432 per Q tile (hi or lo)
#define AT_KV (64 * AT_PITCH)             // 9216 per K/V tile
#define AT_STAGE (3 * AT_KV)              // Kh, Vh, Vl = 27648
#define AT_SMEM (2 * AT_Q + 2 * AT_STAGE) // 92160

__global__ __launch_bounds__(256)
void attn_mma(const __half* __restrict__ qh, const __half* __restrict__ ql,
              const __half* __restrict__ kh,
              const __half* __restrict__ vh, const __half* __restrict__ vl,
              __half* __restrict__ oh, __half* __restrict__ ol)
{
    extern __shared__ char smem[];
    const uint32_t sb = smem_u32(smem);
    const int tid = threadIdx.x;
    const int wid = tid >> 5, lane = tid & 31;

    const int mtile = (int)(gridDim.x - 1 - blockIdx.x);   // heavy CTAs first
    const int bh = blockIdx.y;
    const int m0 = mtile * 128;
    const int ntmax = 2 * mtile + 1;
    const size_t hbase = (size_t)bh * SS * DD;
    const __half* qhp = qh + hbase;
    const __half* qlp = ql + hbase;
    const __half* khp = kh + hbase;
    const __half* vhp = vh + hbase;
    const __half* vlp = vl + hbase;

    // ---- load Q tile (hi+lo) ----
#pragma unroll
    for (int i = 0; i < 4; i++) {
        int cid = tid + i * 256;           // 0..1023
        int row = cid >> 3;
        int j   = cid & 7;
        uint32_t off = (uint32_t)(row * AT_PITCH + j * 16);
        size_t g = (size_t)(m0 + row) * DD + j * 8;
        cp_async16(sb + off, qhp + g);
        cp_async16(sb + AT_Q + off, qlp + g);
    }
    cp_commit();

    auto load_kv = [&](int t) {
        if (t <= ntmax) {
            uint32_t base = sb + 2 * AT_Q + (uint32_t)(t & 1) * AT_STAGE;
            int n0 = t * 64;
#pragma unroll
            for (int i = 0; i < 2; i++) {
                int cid = tid + i * 256;       // 0..511
                int row = cid >> 3;
                int j   = cid & 7;
                uint32_t off = (uint32_t)(row * AT_PITCH + j * 16);
                size_t g = (size_t)(n0 + row) * DD + j * 8;
                cp_async16(base + 0 * AT_KV + off, khp + g);
                cp_async16(base + 1 * AT_KV + off, vhp + g);
                cp_async16(base + 2 * AT_KV + off, vlp + g);
            }
        }
        cp_commit();
    };
    load_kv(0);
    load_kv(1);

    float oacc[8][4];
#pragma unroll
    for (int d = 0; d < 8; d++)
#pragma unroll
        for (int j = 0; j < 4; j++) oacc[d][j] = 0.f;
    float mi0 = -1e30f, mi1 = -1e30f, li0 = 0.f, li1 = 0.f;
    uint32_t qfh[4][4], qfl[4][4];

    const int wr0 = m0 + wid * 16;     // warp's first global Q row

    for (int nt = 0; nt <= ntmax; nt++) {
        cp_wait1();
        __syncthreads();               // stage nt (and Q at nt=0) visible

        if (nt == 0) {                 // load Q fragments once
#pragma unroll
            for (int kc = 0; kc < 4; kc++) {
                uint32_t a = sb + (uint32_t)((wid * 16 + (lane & 15)) * AT_PITCH)
                           + (uint32_t)(kc * 32) + (uint32_t)((lane >> 4) * 16);
                ldsm_x4(qfh[kc], a);
                ldsm_x4(qfl[kc], a + AT_Q);
            }
        }

        const int n0 = nt * 64;
        const int climit = wr0 + 15;   // last valid column for this warp
        if (n0 <= climit) {            // warp has unmasked rows in this tile
            const bool part = (n0 + 63 > wr0);   // partial (diagonal band) tile
            const uint32_t kvb = sb + 2 * AT_Q + (uint32_t)(nt & 1) * AT_STAGE;

            // ---- S = (Qh+Ql) Kh; skip fully-masked 16-col strips ----
            float sacc[8][4];
#pragma unroll
            for (int t8 = 0; t8 < 8; t8++)
#pragma unroll
                for (int j = 0; j < 4; j++) sacc[t8][j] = 0.f;

#pragma unroll
            for (int kc = 0; kc < 4; kc++) {
                uint32_t colo = (uint32_t)(kc * 32) + (uint32_t)((lane >> 4) * 16);
#pragma unroll
                for (int st = 0; st < 4; st++) {
                    if (!part || n0 + st * 16 <= climit) {
                        uint32_t a = kvb + (uint32_t)((st * 16 + (lane & 15)) * AT_PITCH) + colo;
                        uint32_t k4[4];
                        ldsm_x4(k4, a);
                        mma16816h(sacc[2 * st],     qfh[kc], k4[0], k4[2]);
                        mma16816h(sacc[2 * st],     qfl[kc], k4[0], k4[2]);
                        mma16816h(sacc[2 * st + 1], qfh[kc], k4[1], k4[3]);
                        mma16816h(sacc[2 * st + 1], qfl[kc], k4[1], k4[3]);
                    }
                }
            }

            // ---- causal mask (partial tiles only; skipped strips -> -inf) ----
            const int rr0 = wr0 + (lane >> 2);
            if (part) {
#pragma unroll
                for (int t8 = 0; t8 < 8; t8++) {
                    int c0 = n0 + t8 * 8 + 2 * (lane & 3);
                    if (c0     > rr0)     sacc[t8][0] = -1e30f;
                    if (c0 + 1 > rr0)     sacc[t8][1] = -1e30f;
                    if (c0     > rr0 + 8) sacc[t8][2] = -1e30f;
                    if (c0 + 1 > rr0 + 8) sacc[t8][3] = -1e30f;
                }
            }

            // ---- online softmax (rows lane/4 and lane/4+8) ----
            float mx0 = -1e30f, mx1 = -1e30f;
#pragma unroll
            for (int t8 = 0; t8 < 8; t8++) {
                mx0 = fmaxf(mx0, fmaxf(sacc[t8][0], sacc[t8][1]));
                mx1 = fmaxf(mx1, fmaxf(sacc[t8][2], sacc[t8][3]));
            }
            mx0 = fmaxf(mx0, __shfl_xor_sync(0xffffffffu, mx0, 1));
            mx0 = fmaxf(mx0, __shfl_xor_sync(0xffffffffu, mx0, 2));
            mx1 = fmaxf(mx1, __shfl_xor_sync(0xffffffffu, mx1, 1));
            mx1 = fmaxf(mx1, __shfl_xor_sync(0xffffffffu, mx1, 2));
            float mn0 = fmaxf(mi0, mx0), mn1 = fmaxf(mi1, mx1);
            float al0 = __expf(mi0 - mn0), al1 = __expf(mi1 - mn1);
            mi0 = mn0; mi1 = mn1;
            float s0 = 0.f, s1 = 0.f;
#pragma unroll
            for (int t8 = 0; t8 < 8; t8++) {
                float p0 = __expf(sacc[t8][0] - mn0);
                float p1 = __expf(sacc[t8][1] - mn0);
                float p2 = __expf(sacc[t8][2] - mn1);
                float p3 = __expf(sacc[t8][3] - mn1);
                sacc[t8][0] = p0; sacc[t8][1] = p1;
                sacc[t8][2] = p2; sacc[t8][3] = p3;
                s0 += p0 + p1; s1 += p2 + p3;
            }
            li0 = li0 * al0 + s0;        // lane-partial row sums
            li1 = li1 * al1 + s1;
#pragma unroll
            for (int d = 0; d < 8; d++) {
                oacc[d][0] *= al0; oacc[d][1] *= al0;
                oacc[d][2] *= al1; oacc[d][3] *= al1;
            }

            // ---- P -> single fp16 A-fragments (no split) ----
            uint32_t aP[4][4];
#pragma unroll
            for (int kc = 0; kc < 4; kc++) {
                aP[kc][0] = hpack(sacc[2 * kc][0],     sacc[2 * kc][1]);
                aP[kc][1] = hpack(sacc[2 * kc][2],     sacc[2 * kc][3]);
                aP[kc][2] = hpack(sacc[2 * kc + 1][0], sacc[2 * kc + 1][1]);
                aP[kc][3] = hpack(sacc[2 * kc + 1][2], sacc[2 * kc + 1][3]);
            }

            // ---- O += Ph (Vh + Vl); skip all-masked strips ----
            const uint32_t vhb = kvb + 1 * AT_KV;
            const uint32_t vlb = kvb + 2 * AT_KV;
#pragma unroll
            for (int kc = 0; kc < 4; kc++) {
                if (!part || n0 + kc * 16 <= climit) {
#pragma unroll
                    for (int vp = 0; vp < 4; vp++) {
                        uint32_t off = (uint32_t)((kc * 16 + (lane & 15)) * AT_PITCH)
                                     + (uint32_t)(vp * 32) + (uint32_t)((lane >> 4) * 16);
                        uint32_t v4h[4], v4l[4];
                        ldsm_x4_t(v4h, vhb + off);
                        ldsm_x4_t(v4l, vlb + off);
                        mma16816h(oacc[2 * vp],     aP[kc], v4h[0], v4h[1]);
                        mma16816h(oacc[2 * vp],     aP[kc], v4l[0], v4l[1]);
                        mma16816h(oacc[2 * vp + 1], aP[kc], v4h[2], v4h[3]);
                        mma16816h(oacc[2 * vp + 1], aP[kc], v4l[2], v4l[3]);
                    }
                }
            }
        }

        __syncthreads();               // all warps done reading slot nt&1
        load_kv(nt + 2);
    }

    // ---- normalize + write split fp16 output [m][E] at cols h*64.. ----
    li0 += __shfl_xor_sync(0xffffffffu, li0, 1);
    li0 += __shfl_xor_sync(0xffffffffu, li0, 2);
    li1 += __shfl_xor_sync(0xffffffffu, li1, 1);
    li1 += __shfl_xor_sync(0xffffffffu, li1, 2);
    const float inv0 = 1.f / li0, inv1 = 1.f / li1;

    const int b_ = bh / HH, h_ = bh % HH;
    const int r0g = m0 + wid * 16 + (lane >> 2);
#pragma unroll
    for (int dt = 0; dt < 8; dt++) {
        int col = h_ * 64 + dt * 8 + 2 * (lane & 3);
        size_t o0 = (size_t)(b_ * SS + r0g) * EE + col;
        size_t o1 = (size_t)(b_ * SS + r0g + 8) * EE + col;
        uint32_t hreg, lreg;
        hpsplit(oacc[dt][0] * inv0, oacc[dt][1] * inv0, hreg, lreg);
        *(uint32_t*)&oh[o0] = hreg;
        *(uint32_t*)&ol[o0] = lreg;
        hpsplit(oacc[dt][2] * inv1, oacc[dt][3] * inv1, hreg, lreg);
        *(uint32_t*)&oh[o1] = hreg;
        *(uint32_t*)&ol[o1] = lreg;
    }
}

// ---------------------------------------------------------------------------
extern "C" void kernel_launch(void* const* d_in, const int* in_sizes, int n_in,
                              void* d_out, int out_size)
{
    (void)in_sizes; (void)n_in; (void)out_size;
    const float* x  = (const float*)d_in[0];
    const float* Wq = (const float*)d_in[1];
    const float* bq = (const float*)d_in[2];
    const float* Wk = (const float*)d_in[3];
    const float* bk = (const float*)d_in[4];
    const float* Wv = (const float*)d_in[5];
    const float* bv = (const float*)d_in[6];
    const float* Wp = (const float*)d_in[7];
    const float* bp = (const float*)d_in[8];

    __half *ah, *al, *wt, *qh, *ql, *kh, *vh, *vl;
    cudaGetSymbolAddress((void**)&ah, g_ah);
    cudaGetSymbolAddress((void**)&al, g_al);
    cudaGetSymbolAddress((void**)&wt, g_wt);
    cudaGetSymbolAddress((void**)&qh, g_qh);
    cudaGetSymbolAddress((void**)&ql, g_ql);
    cudaGetSymbolAddress((void**)&kh, g_kh);
    cudaGetSymbolAddress((void**)&vh, g_vh);
    cudaGetSymbolAddress((void**)&vl, g_vl);

    cudaFuncSetAttribute(gemm_mma<1>,
                         cudaFuncAttributeMaxDynamicSharedMemorySize, GM_SMEM);
    cudaFuncSetAttribute(gemm_mma<0>,
                         cudaFuncAttributeMaxDynamicSharedMemorySize, GM_SMEM);
    cudaFuncSetAttribute(attn_mma,
                         cudaFuncAttributeMaxDynamicSharedMemorySize, AT_SMEM);

    // Split x into fp16 hi/lo; transpose weights to fp16 [n][k]
    split_convert<<<(MT * EE + 255) / 256, 256>>>(x, ah, al, MT * EE);
    transpose_w<<<dim3(EE / 32, EE / 32, 4), 256>>>(Wq, Wk, Wv, Wp, wt);

    // Fused Q/K/V projections + bias + RoPE + fp16 pack -> [B,H,S,D]
    gemm_mma<1><<<dim3(EE / 128, MT / 128, 3), 256, GM_SMEM>>>(
        ah, al, wt, bq, bk, bv, nullptr, nullptr,
        qh, ql, kh, vh, vl);

    // fp16 tensor-core causal flash attention -> fp16 hi/lo [B,S,E] (ah/al)
    attn_mma<<<dim3(SS / 128, BB * HH), 256, AT_SMEM>>>(
        qh, ql, kh, vh, vl, ah, al);

    // Output projection -> d_out
    gemm_mma<0><<<dim3(EE / 128, MT / 128, 1), 256, GM_SMEM>>>(
        ah, al, wt, nullptr, nullptr, nullptr, bp, (float*)d_out,
        nullptr, nullptr, nullptr, nullptr, nullptr);
}

// round 15
// speedup vs baseline: 1.6119x; 1.0326x over previous
#include <cuda_runtime.h>
#include <cuda_bf16.h>
#include <cuda_fp16.h>
#include <math.h>
#include <stdint.h>

#define BB 2
#define SS 2048
#define EE 768
#define HH 12
#define DD 64
#define MT (BB*SS)

// ---------------------------------------------------------------------------
// Scratch (allocation-free rule: __device__ globals)
// ---------------------------------------------------------------------------
__device__ __half g_ah[(size_t)MT*EE];             // GEMM A hi (x, then attn out)
__device__ __half g_al[(size_t)MT*EE];             // GEMM A lo
__device__ __half g_wt[(size_t)4*EE*EE];           // [4][n][k] = W[k][n], fp16
__device__ __half g_qh[(size_t)BB*HH*SS*DD];       // fp16 q hi
__device__ __half g_ql[(size_t)BB*HH*SS*DD];       // fp16 q lo (residual)
__device__ __half g_kh[(size_t)BB*HH*SS*DD];       // fp16 0.125*k (single)
__device__ __half g_vh[(size_t)BB*HH*SS*DD];       // fp16 v hi
__device__ __half g_vl[(size_t)BB*HH*SS*DD];       // fp16 v lo

// ---------------------------------------------------------------------------
// PTX helpers (BASE ISA ONLY — harness ptxas targets sm_103 without 'a')
// ---------------------------------------------------------------------------
__device__ __forceinline__ uint32_t smem_u32(const void* p) {
    uint32_t a;
    asm("{ .reg .u64 t; cvta.to.shared.u64 t, %1; cvt.u32.u64 %0, t; }"
        : "=r"(a) : "l"(p));
    return a;
}
__device__ __forceinline__ void cp_async16(uint32_t saddr, const void* gaddr) {
    asm volatile("cp.async.cg.shared.global [%0], [%1], 16;"
                 :: "r"(saddr), "l"(gaddr) : "memory");
}
__device__ __forceinline__ void cp_commit() {
    asm volatile("cp.async.commit_group;" ::: "memory");
}
__device__ __forceinline__ void cp_wait1() {
    asm volatile("cp.async.wait_group 1;" ::: "memory");
}
__device__ __forceinline__ void cp_wait0() {
    asm volatile("cp.async.wait_group 0;" ::: "memory");
}
__device__ __forceinline__ void ldsm_x4(uint32_t* r, uint32_t addr) {
    asm volatile("ldmatrix.sync.aligned.m8n8.x4.shared.b16 {%0,%1,%2,%3}, [%4];"
                 : "=r"(r[0]), "=r"(r[1]), "=r"(r[2]), "=r"(r[3]) : "r"(addr));
}
__device__ __forceinline__ void ldsm_x4_t(uint32_t* r, uint32_t addr) {
    asm volatile("ldmatrix.sync.aligned.m8n8.x4.trans.shared.b16 {%0,%1,%2,%3}, [%4];"
                 : "=r"(r[0]), "=r"(r[1]), "=r"(r[2]), "=r"(r[3]) : "r"(addr));
}
// fp16 mma
__device__ __forceinline__ void mma16816h(float* c, const uint32_t* a,
                                          uint32_t b0, uint32_t b1) {
    asm volatile(
        "mma.sync.aligned.m16n8k16.row.col.f32.f16.f16.f32 "
        "{%0,%1,%2,%3}, {%4,%5,%6,%7}, {%8,%9}, {%0,%1,%2,%3};"
        : "+f"(c[0]), "+f"(c[1]), "+f"(c[2]), "+f"(c[3])
        : "r"(a[0]), "r"(a[1]), "r"(a[2]), "r"(a[3]), "r"(b0), "r"(b1));
}
// fp16 split + pack
__device__ __forceinline__ void hpsplit(float p0, float p1,
                                        uint32_t& hreg, uint32_t& lreg) {
    __half2 hh = __floats2half2_rn(p0, p1);
    float r0 = p0 - __low2float(hh);
    float r1 = p1 - __high2float(hh);
    __half2 ll = __floats2half2_rn(r0, r1);
    hreg = *reinterpret_cast<uint32_t*>(&hh);
    lreg = *reinterpret_cast<uint32_t*>(&ll);
}
__device__ __forceinline__ uint32_t hpack(float p0, float p1) {
    __half2 hh = __floats2half2_rn(p0, p1);
    return *reinterpret_cast<uint32_t*>(&hh);
}
__device__ __forceinline__ void hsplit(float x, __half& h, __half& l) {
    h = __float2half_rn(x);
    l = __float2half_rn(x - __half2float(h));
}

// ---------------------------------------------------------------------------
// Precision-split conversion: x -> (fp16 hi, fp16 lo)
// ---------------------------------------------------------------------------
__global__ __launch_bounds__(256)
void split_convert(const float* __restrict__ in, __half* __restrict__ h,
                   __half* __restrict__ l, int n)
{
    int i = blockIdx.x * blockDim.x + threadIdx.x;
    if (i < n) {
        __half hi, lo;
        hsplit(in[i], hi, lo);
        h[i] = hi;
        l[i] = lo;
    }
}

// Transpose: Wt[z][n][k] = W_z[k][n]  (single fp16)
__global__ __launch_bounds__(256)
void transpose_w(const float* __restrict__ W0, const float* __restrict__ W1,
                 const float* __restrict__ W2, const float* __restrict__ W3,
                 __half* __restrict__ th)
{
    __shared__ float t[32][33];
    const float* W = (blockIdx.z == 0) ? W0 : (blockIdx.z == 1) ? W1
                   : (blockIdx.z == 2) ? W2 : W3;
    int n0 = blockIdx.x * 32, k0 = blockIdx.y * 32;
    int tx = threadIdx.x & 31, ty = threadIdx.x >> 5;
#pragma unroll
    for (int i = 0; i < 4; i++)
        t[ty + 8 * i][tx] = W[(size_t)(k0 + ty + 8 * i) * EE + n0 + tx];
    __syncthreads();
    size_t base = (size_t)blockIdx.z * EE * EE;
#pragma unroll
    for (int i = 0; i < 4; i++) {
        int row = ty + 8 * i;                 // local n
        th[base + (size_t)(n0 + row) * EE + k0 + tx] = __float2half_rn(t[tx][row]);
    }
}

// ---------------------------------------------------------------------------
// fp16 mma.sync GEMM: C = A @ W + bias.  A = fp16 hi+lo (exact to 2^-22),
// W = single fp16 (error = W rounding ~2^-12).  2 MMAs per k-step.
// CTA 128x128, 8 warps of 32x64, K-chunk 64 (halved sync count),
// 2-stage cp.async, occupancy 2 (2 x 110592 B smem).
// MODE 0: fp32 C[m*EE+n] to fout.
// MODE 1: fused epilogue — bias + RoPE (smem trig table) + fp16 outputs:
//         q -> fp16 hi/lo (unscaled), k -> fp16 single (x0.125), v -> hi/lo.
// ---------------------------------------------------------------------------
#define KC 64
#define NCH (EE / KC)                 // 12
#define GM_PITCH 144                  // 64 halves = 128B data + 16B pad
#define GM_TILE (128 * GM_PITCH)      // 18432
#define GM_BUF (3 * GM_TILE)          // Ah, Al, B = 55296
#define GM_SMEM (2 * GM_BUF)          // 110592 -> 2 CTAs/SM (221184 total)

template<int MODE>
__global__ __launch_bounds__(256, 2)
void gemm_mma(const __half* __restrict__ Ah, const __half* __restrict__ Al,
              const __half* __restrict__ Wt,
              const float* b0, const float* b1, const float* b2, const float* b3,
              float* fout,
              __half* qh, __half* ql, __half* kh, __half* vh, __half* vl)
{
    extern __shared__ char smem[];
    const uint32_t sb = smem_u32(smem);
    const int tid = threadIdx.x;
    const int wid = tid >> 5, lane = tid & 31;
    const int wm = wid & 3;          // 4 m-groups of 32 rows
    const int wn = wid >> 2;         // 2 n-groups of 64 cols

    const int wsel = (MODE == 1) ? (int)blockIdx.z : 3;
    const float* bias = (wsel == 0) ? b0 : (wsel == 1) ? b1 : (wsel == 2) ? b2 : b3;
    const __half* Bw = Wt + (size_t)wsel * EE * EE;
    const int m0 = blockIdx.y * 128;
    const int n0 = blockIdx.x * 128;

    auto load_chunk = [&](int c) {
        uint32_t buf = sb + (uint32_t)(c & 1) * GM_BUF;
        int k0 = c * KC;
#pragma unroll
        for (int i = 0; i < 4; i++) {
            int idx = tid + i * 256;            // 0..1023
            int row = idx >> 3;                 // 0..127
            int j   = idx & 7;                  // 16B quad (64 halves per row)
            uint32_t off = (uint32_t)(row * GM_PITCH + j * 16);
            size_t ga = (size_t)(m0 + row) * EE + k0 + j * 8;
            size_t gb = (size_t)(n0 + row) * EE + k0 + j * 8;
            cp_async16(buf + 0 * GM_TILE + off, Ah + ga);
            cp_async16(buf + 1 * GM_TILE + off, Al + ga);
            cp_async16(buf + 2 * GM_TILE + off, Bw + gb);
        }
        cp_commit();
    };

    float acc[2][8][4];
#pragma unroll
    for (int mt = 0; mt < 2; mt++)
#pragma unroll
        for (int nt = 0; nt < 8; nt++)
#pragma unroll
            for (int i = 0; i < 4; i++) acc[mt][nt][i] = 0.f;

    load_chunk(0);
    load_chunk(1);

    const int rA = wm * 32 + (lane & 15);
    const int rB = wn * 64 + (lane & 15);
    const uint32_t chalf = (uint32_t)((lane >> 4) * 16);

    for (int c = 0; c < NCH; c++) {
        cp_wait1();            // chunk c resident
        __syncthreads();
        uint32_t buf = sb + (uint32_t)(c & 1) * GM_BUF;

#pragma unroll
        for (int ks = 0; ks < 4; ks++) {
            uint32_t colo = (uint32_t)(ks * 32) + chalf;
            uint32_t ah[2][4], al[2][4], bw[4][4];
#pragma unroll
            for (int mt = 0; mt < 2; mt++) {
                uint32_t off = (uint32_t)((rA + mt * 16) * GM_PITCH) + colo;
                ldsm_x4(ah[mt], buf + 0 * GM_TILE + off);
                ldsm_x4(al[mt], buf + 1 * GM_TILE + off);
            }
#pragma unroll
            for (int p = 0; p < 4; p++) {
                uint32_t off = (uint32_t)((rB + p * 16) * GM_PITCH) + colo;
                ldsm_x4(bw[p], buf + 2 * GM_TILE + off);
            }
#pragma unroll
            for (int mt = 0; mt < 2; mt++)
#pragma unroll
                for (int nt = 0; nt < 8; nt++) {
                    const int p = nt >> 1, q = nt & 1;
                    mma16816h(acc[mt][nt], ah[mt], bw[p][q], bw[p][q + 2]);
                    mma16816h(acc[mt][nt], al[mt], bw[p][q], bw[p][q + 2]);
                }
        }

        __syncthreads();       // all warps done reading slot c&1
        if (c + 2 < NCH) load_chunk(c + 2);
        else cp_commit();
    }

    if (MODE == 0) {
        // plain fp32 epilogue (output projection -> d_out)
        const int mrow0 = m0 + wm * 32;
#pragma unroll
        for (int mt = 0; mt < 2; mt++) {
#pragma unroll
            for (int nt = 0; nt < 8; nt++) {
                int gn = n0 + wn * 64 + nt * 8 + 2 * (lane & 3);
                float2 bv = *(const float2*)&bias[gn];
                int r0 = mrow0 + mt * 16 + (lane >> 2);
                float2 v0 = { acc[mt][nt][0] + bv.x, acc[mt][nt][1] + bv.y };
                float2 v1 = { acc[mt][nt][2] + bv.x, acc[mt][nt][3] + bv.y };
                *(float2*)&fout[(size_t)r0 * EE + gn] = v0;
                *(float2*)&fout[(size_t)(r0 + 8) * EE + gn] = v1;
            }
        }
    } else {
        // fused bias + RoPE + fp16 pack epilogue
        __half *dh, *dl;
        if (wsel == 0)      { dh = qh; dl = ql; }
        else if (wsel == 1) { dh = kh; dl = nullptr; }
        else                { dh = vh; dl = vl; }
        const int hh = (int)blockIdx.x * 2 + wn;     // head index
        const int c2 = 2 * (lane & 3);
        const float RC = 0.28782313662425572f;       // ln(10000)/32

        float2* tab = (float2*)smem;                 // reuse dead stage buffers
        if (wsel < 2) {
            cp_wait0();
            __syncthreads();                         // stage buffers now dead
            for (int idx = tid; idx < 128 * 32; idx += 256) {
                int rl = idx >> 5, i = idx & 31;
                int s = (m0 + rl) & (SS - 1);
                float ang = (float)s * expf(-(float)i * RC);
                float sn, cs;
                sincosf(ang, &sn, &cs);
                tab[idx] = make_float2(cs, sn);
            }
            __syncthreads();
        }

#pragma unroll
        for (int mt = 0; mt < 2; mt++) {
#pragma unroll
            for (int rr = 0; rr < 2; rr++) {
                int rloc = wm * 32 + mt * 16 + (lane >> 2) + rr * 8;
                int r = m0 + rloc;
                int b_ = r >> 11, s = r & (SS - 1);
                float vals[8][2];
#pragma unroll
                for (int nt = 0; nt < 8; nt++) {
                    float2 bv = *(const float2*)&bias[hh * 64 + nt * 8 + c2];
                    vals[nt][0] = acc[mt][nt][2 * rr]     + bv.x;
                    vals[nt][1] = acc[mt][nt][2 * rr + 1] + bv.y;
                }
                if (wsel < 2) {
#pragma unroll
                    for (int nt = 0; nt < 4; nt++) {
#pragma unroll
                        for (int cc = 0; cc < 2; cc++) {
                            int i = nt * 8 + c2 + cc;
                            float2 cs = tab[rloc * 32 + i];
                            float x = vals[nt][cc], y = vals[nt + 4][cc];
                            vals[nt][cc]     = x * cs.x - y * cs.y;
                            vals[nt + 4][cc] = y * cs.x + x * cs.y;
                        }
                    }
                    if (wsel == 1) {                 // fold 1/sqrt(D) into K
#pragma unroll
                        for (int nt = 0; nt < 8; nt++) {
                            vals[nt][0] *= 0.125f;
                            vals[nt][1] *= 0.125f;
                        }
                    }
                }
                size_t rowb = ((size_t)(b_ * HH + hh) * SS + s) * DD;
                if (wsel == 1) {                     // k: single fp16
#pragma unroll
                    for (int nt = 0; nt < 8; nt++)
                        *(uint32_t*)&dh[rowb + nt * 8 + c2] =
                            hpack(vals[nt][0], vals[nt][1]);
                } else {                             // q/v: fp16 hi + lo
#pragma unroll
                    for (int nt = 0; nt < 8; nt++) {
                        uint32_t hreg, lreg;
                        hpsplit(vals[nt][0], vals[nt][1], hreg, lreg);
                        *(uint32_t*)&dh[rowb + nt * 8 + c2] = hreg;
                        *(uint32_t*)&dl[rowb + nt * 8 + c2] = lreg;
                    }
                }
            }
        }
    }
}

// ---------------------------------------------------------------------------
// Tensor-core causal flash attention — fp16 path, occupancy 2.
// S = (Qh+Ql)·Kh ; O += Ph·(Vh+Vl).  Output fp16 hi/lo (feeds fp16 GEMM).
// Natural reg use is 128 (ncu R14) so the occ-2 cap costs nothing;
// 2 x 92160 B smem = 184320 fits the carveout.
// ---------------------------------------------------------------------------
#define AT_PITCH 144                      // 64 halves = 128B data + 16B pad
#define AT_Q (128 * AT_PITCH)             // 18432 per Q tile (hi or lo)
#define AT_KV (64 * AT_PITCH)             // 9216 per K/V tile
#define AT_STAGE (3 * AT_KV)              // Kh, Vh, Vl = 27648
#define AT_SMEM (2 * AT_Q + 2 * AT_STAGE) // 92160

__global__ __launch_bounds__(256, 2)
void attn_mma(const __half* __restrict__ qh, const __half* __restrict__ ql,
              const __half* __restrict__ kh,
              const __half* __restrict__ vh, const __half* __restrict__ vl,
              __half* __restrict__ oh, __half* __restrict__ ol)
{
    extern __shared__ char smem[];
    const uint32_t sb = smem_u32(smem);
    const int tid = threadIdx.x;
    const int wid = tid >> 5, lane = tid & 31;

    const int mtile = (int)(gridDim.x - 1 - blockIdx.x);   // heavy CTAs first
    const int bh = blockIdx.y;
    const int m0 = mtile * 128;
    const int ntmax = 2 * mtile + 1;
    const size_t hbase = (size_t)bh * SS * DD;
    const __half* qhp = qh + hbase;
    const __half* qlp = ql + hbase;
    const __half* khp = kh + hbase;
    const __half* vhp = vh + hbase;
    const __half* vlp = vl + hbase;

    // ---- load Q tile (hi+lo) ----
#pragma unroll
    for (int i = 0; i < 4; i++) {
        int cid = tid + i * 256;           // 0..1023
        int row = cid >> 3;
        int j   = cid & 7;
        uint32_t off = (uint32_t)(row * AT_PITCH + j * 16);
        size_t g = (size_t)(m0 + row) * DD + j * 8;
        cp_async16(sb + off, qhp + g);
        cp_async16(sb + AT_Q + off, qlp + g);
    }
    cp_commit();

    auto load_kv = [&](int t) {
        if (t <= ntmax) {
            uint32_t base = sb + 2 * AT_Q + (uint32_t)(t & 1) * AT_STAGE;
            int n0 = t * 64;
#pragma unroll
            for (int i = 0; i < 2; i++) {
                int cid = tid + i * 256;       // 0..511
                int row = cid >> 3;
                int j   = cid & 7;
                uint32_t off = (uint32_t)(row * AT_PITCH + j * 16);
                size_t g = (size_t)(n0 + row) * DD + j * 8;
                cp_async16(base + 0 * AT_KV + off, khp + g);
                cp_async16(base + 1 * AT_KV + off, vhp + g);
                cp_async16(base + 2 * AT_KV + off, vlp + g);
            }
        }
        cp_commit();
    };
    load_kv(0);
    load_kv(1);

    float oacc[8][4];
#pragma unroll
    for (int d = 0; d < 8; d++)
#pragma unroll
        for (int j = 0; j < 4; j++) oacc[d][j] = 0.f;
    float mi0 = -1e30f, mi1 = -1e30f, li0 = 0.f, li1 = 0.f;
    uint32_t qfh[4][4], qfl[4][4];

    const int wr0 = m0 + wid * 16;     // warp's first global Q row

    for (int nt = 0; nt <= ntmax; nt++) {
        cp_wait1();
        __syncthreads();               // stage nt (and Q at nt=0) visible

        if (nt == 0) {                 // load Q fragments once
#pragma unroll
            for (int kc = 0; kc < 4; kc++) {
                uint32_t a = sb + (uint32_t)((wid * 16 + (lane & 15)) * AT_PITCH)
                           + (uint32_t)(kc * 32) + (uint32_t)((lane >> 4) * 16);
                ldsm_x4(qfh[kc], a);
                ldsm_x4(qfl[kc], a + AT_Q);
            }
        }

        const int n0 = nt * 64;
        const int climit = wr0 + 15;   // last valid column for this warp
        if (n0 <= climit) {            // warp has unmasked rows in this tile
            const bool part = (n0 + 63 > wr0);   // partial (diagonal band) tile
            const uint32_t kvb = sb + 2 * AT_Q + (uint32_t)(nt & 1) * AT_STAGE;

            // ---- S = (Qh+Ql) Kh; skip fully-masked 16-col strips ----
            float sacc[8][4];
#pragma unroll
            for (int t8 = 0; t8 < 8; t8++)
#pragma unroll
                for (int j = 0; j < 4; j++) sacc[t8][j] = 0.f;

#pragma unroll
            for (int kc = 0; kc < 4; kc++) {
                uint32_t colo = (uint32_t)(kc * 32) + (uint32_t)((lane >> 4) * 16);
#pragma unroll
                for (int st = 0; st < 4; st++) {
                    if (!part || n0 + st * 16 <= climit) {
                        uint32_t a = kvb + (uint32_t)((st * 16 + (lane & 15)) * AT_PITCH) + colo;
                        uint32_t k4[4];
                        ldsm_x4(k4, a);
                        mma16816h(sacc[2 * st],     qfh[kc], k4[0], k4[2]);
                        mma16816h(sacc[2 * st],     qfl[kc], k4[0], k4[2]);
                        mma16816h(sacc[2 * st + 1], qfh[kc], k4[1], k4[3]);
                        mma16816h(sacc[2 * st + 1], qfl[kc], k4[1], k4[3]);
                    }
                }
            }

            // ---- causal mask (partial tiles only; skipped strips -> -inf) ----
            const int rr0 = wr0 + (lane >> 2);
            if (part) {
#pragma unroll
                for (int t8 = 0; t8 < 8; t8++) {
                    int c0 = n0 + t8 * 8 + 2 * (lane & 3);
                    if (c0     > rr0)     sacc[t8][0] = -1e30f;
                    if (c0 + 1 > rr0)     sacc[t8][1] = -1e30f;
                    if (c0     > rr0 + 8) sacc[t8][2] = -1e30f;
                    if (c0 + 1 > rr0 + 8) sacc[t8][3] = -1e30f;
                }
            }

            // ---- online softmax (rows lane/4 and lane/4+8) ----
            float mx0 = -1e30f, mx1 = -1e30f;
#pragma unroll
            for (int t8 = 0; t8 < 8; t8++) {
                mx0 = fmaxf(mx0, fmaxf(sacc[t8][0], sacc[t8][1]));
                mx1 = fmaxf(mx1, fmaxf(sacc[t8][2], sacc[t8][3]));
            }
            mx0 = fmaxf(mx0, __shfl_xor_sync(0xffffffffu, mx0, 1));
            mx0 = fmaxf(mx0, __shfl_xor_sync(0xffffffffu, mx0, 2));
            mx1 = fmaxf(mx1, __shfl_xor_sync(0xffffffffu, mx1, 1));
            mx1 = fmaxf(mx1, __shfl_xor_sync(0xffffffffu, mx1, 2));
            float mn0 = fmaxf(mi0, mx0), mn1 = fmaxf(mi1, mx1);
            float al0 = __expf(mi0 - mn0), al1 = __expf(mi1 - mn1);
            mi0 = mn0; mi1 = mn1;
            float s0 = 0.f, s1 = 0.f;
#pragma unroll
            for (int t8 = 0; t8 < 8; t8++) {
                float p0 = __expf(sacc[t8][0] - mn0);
                float p1 = __expf(sacc[t8][1] - mn0);
                float p2 = __expf(sacc[t8][2] - mn1);
                float p3 = __expf(sacc[t8][3] - mn1);
                sacc[t8][0] = p0; sacc[t8][1] = p1;
                sacc[t8][2] = p2; sacc[t8][3] = p3;
                s0 += p0 + p1; s1 += p2 + p3;
            }
            li0 = li0 * al0 + s0;        // lane-partial row sums
            li1 = li1 * al1 + s1;
#pragma unroll
            for (int d = 0; d < 8; d++) {
                oacc[d][0] *= al0; oacc[d][1] *= al0;
                oacc[d][2] *= al1; oacc[d][3] *= al1;
            }

            // ---- P -> single fp16 A-fragments (no split) ----
            uint32_t aP[4][4];
#pragma unroll
            for (int kc = 0; kc < 4; kc++) {
                aP[kc][0] = hpack(sacc[2 * kc][0],     sacc[2 * kc][1]);
                aP[kc][1] = hpack(sacc[2 * kc][2],     sacc[2 * kc][3]);
                aP[kc][2] = hpack(sacc[2 * kc + 1][0], sacc[2 * kc + 1][1]);
                aP[kc][3] = hpack(sacc[2 * kc + 1][2], sacc[2 * kc + 1][3]);
            }

            // ---- O += Ph (Vh + Vl); skip all-masked strips ----
            const uint32_t vhb = kvb + 1 * AT_KV;
            const uint32_t vlb = kvb + 2 * AT_KV;
#pragma unroll
            for (int kc = 0; kc < 4; kc++) {
                if (!part || n0 + kc * 16 <= climit) {
#pragma unroll
                    for (int vp = 0; vp < 4; vp++) {
                        uint32_t off = (uint32_t)((kc * 16 + (lane & 15)) * AT_PITCH)
                                     + (uint32_t)(vp * 32) + (uint32_t)((lane >> 4) * 16);
                        uint32_t v4h[4], v4l[4];
                        ldsm_x4_t(v4h, vhb + off);
                        ldsm_x4_t(v4l, vlb + off);
                        mma16816h(oacc[2 * vp],     aP[kc], v4h[0], v4h[1]);
                        mma16816h(oacc[2 * vp],     aP[kc], v4l[0], v4l[1]);
                        mma16816h(oacc[2 * vp + 1], aP[kc], v4h[2], v4h[3]);
                        mma16816h(oacc[2 * vp + 1], aP[kc], v4l[2], v4l[3]);
                    }
                }
            }
        }

        __syncthreads();               // all warps done reading slot nt&1
        load_kv(nt + 2);
    }

    // ---- normalize + write split fp16 output [m][E] at cols h*64.. ----
    li0 += __shfl_xor_sync(0xffffffffu, li0, 1);
    li0 += __shfl_xor_sync(0xffffffffu, li0, 2);
    li1 += __shfl_xor_sync(0xffffffffu, li1, 1);
    li1 += __shfl_xor_sync(0xffffffffu, li1, 2);
    const float inv0 = 1.f / li0, inv1 = 1.f / li1;

    const int b_ = bh / HH, h_ = bh % HH;
    const int r0g = m0 + wid * 16 + (lane >> 2);
#pragma unroll
    for (int dt = 0; dt < 8; dt++) {
        int col = h_ * 64 + dt * 8 + 2 * (lane & 3);
        size_t o0 = (size_t)(b_ * SS + r0g) * EE + col;
        size_t o1 = (size_t)(b_ * SS + r0g + 8) * EE + col;
        uint32_t hreg, lreg;
        hpsplit(oacc[dt][0] * inv0, oacc[dt][1] * inv0, hreg, lreg);
        *(uint32_t*)&oh[o0] = hreg;
        *(uint32_t*)&ol[o0] = lreg;
        hpsplit(oacc[dt][2] * inv1, oacc[dt][3] * inv1, hreg, lreg);
        *(uint32_t*)&oh[o1] = hreg;
        *(uint32_t*)&ol[o1] = lreg;
    }
}

// ---------------------------------------------------------------------------
extern "C" void kernel_launch(void* const* d_in, const int* in_sizes, int n_in,
                              void* d_out, int out_size)
{
    (void)in_sizes; (void)n_in; (void)out_size;
    const float* x  = (const float*)d_in[0];
    const float* Wq = (const float*)d_in[1];
    const float* bq = (const float*)d_in[2];
    const float* Wk = (const float*)d_in[3];
    const float* bk = (const float*)d_in[4];
    const float* Wv = (const float*)d_in[5];
    const float* bv = (const float*)d_in[6];
    const float* Wp = (const float*)d_in[7];
    const float* bp = (const float*)d_in[8];

    __half *ah, *al, *wt, *qh, *ql, *kh, *vh, *vl;
    cudaGetSymbolAddress((void**)&ah, g_ah);
    cudaGetSymbolAddress((void**)&al, g_al);
    cudaGetSymbolAddress((void**)&wt, g_wt);
    cudaGetSymbolAddress((void**)&qh, g_qh);
    cudaGetSymbolAddress((void**)&ql, g_ql);
    cudaGetSymbolAddress((void**)&kh, g_kh);
    cudaGetSymbolAddress((void**)&vh, g_vh);
    cudaGetSymbolAddress((void**)&vl, g_vl);

    cudaFuncSetAttribute(gemm_mma<1>,
                         cudaFuncAttributeMaxDynamicSharedMemorySize, GM_SMEM);
    cudaFuncSetAttribute(gemm_mma<0>,
                         cudaFuncAttributeMaxDynamicSharedMemorySize, GM_SMEM);
    cudaFuncSetAttribute(attn_mma,
                         cudaFuncAttributeMaxDynamicSharedMemorySize, AT_SMEM);

    // Split x into fp16 hi/lo; transpose weights to fp16 [n][k]
    split_convert<<<(MT * EE + 255) / 256, 256>>>(x, ah, al, MT * EE);
    transpose_w<<<dim3(EE / 32, EE / 32, 4), 256>>>(Wq, Wk, Wv, Wp, wt);

    // Fused Q/K/V projections + bias + RoPE + fp16 pack -> [B,H,S,D]
    gemm_mma<1><<<dim3(EE / 128, MT / 128, 3), 256, GM_SMEM>>>(
        ah, al, wt, bq, bk, bv, nullptr, nullptr,
        qh, ql, kh, vh, vl);

    // fp16 tensor-core causal flash attention -> fp16 hi/lo [B,S,E] (ah/al)
    attn_mma<<<dim3(SS / 128, BB * HH), 256, AT_SMEM>>>(
        qh, ql, kh, vh, vl, ah, al);

    // Output projection -> d_out
    gemm_mma<0><<<dim3(EE / 128, MT / 128, 1), 256, GM_SMEM>>>(
        ah, al, wt, nullptr, nullptr, nullptr, bp, (float*)d_out,
        nullptr, nullptr, nullptr, nullptr, nullptr);
}

// round 17
// speedup vs baseline: 1.9580x; 1.2147x over previous
#include <cuda_runtime.h>
#include <cuda_bf16.h>
#include <cuda_fp16.h>
#include <math.h>
#include <stdint.h>

#define BB 2
#define SS 2048
#define EE 768
#define HH 12
#define DD 64
#define MT (BB*SS)

// ---------------------------------------------------------------------------
// Scratch (allocation-free rule: __device__ globals)
// ---------------------------------------------------------------------------
__device__ __half g_ah[(size_t)MT*EE];             // GEMM A hi (x, then attn out)
__device__ __half g_al[(size_t)MT*EE];             // GEMM A lo
__device__ __half g_wt[(size_t)4*EE*EE];           // [4][n][k] = W[k][n], fp16
__device__ __half g_q16[(size_t)BB*HH*SS*DD];      // fp16 q (single)
__device__ __half g_k16[(size_t)BB*HH*SS*DD];      // fp16 0.125*k (single)
__device__ __half g_v16[(size_t)BB*HH*SS*DD];      // fp16 v (single)

// ---------------------------------------------------------------------------
// PTX helpers (BASE ISA ONLY — harness ptxas targets sm_103 without 'a')
// ---------------------------------------------------------------------------
__device__ __forceinline__ uint32_t smem_u32(const void* p) {
    uint32_t a;
    asm("{ .reg .u64 t; cvta.to.shared.u64 t, %1; cvt.u32.u64 %0, t; }"
        : "=r"(a) : "l"(p));
    return a;
}
__device__ __forceinline__ void cp_async16(uint32_t saddr, const void* gaddr) {
    asm volatile("cp.async.cg.shared.global [%0], [%1], 16;"
                 :: "r"(saddr), "l"(gaddr) : "memory");
}
__device__ __forceinline__ void cp_commit() {
    asm volatile("cp.async.commit_group;" ::: "memory");
}
__device__ __forceinline__ void cp_wait1() {
    asm volatile("cp.async.wait_group 1;" ::: "memory");
}
__device__ __forceinline__ void cp_wait0() {
    asm volatile("cp.async.wait_group 0;" ::: "memory");
}
__device__ __forceinline__ void ldsm_x4(uint32_t* r, uint32_t addr) {
    asm volatile("ldmatrix.sync.aligned.m8n8.x4.shared.b16 {%0,%1,%2,%3}, [%4];"
                 : "=r"(r[0]), "=r"(r[1]), "=r"(r[2]), "=r"(r[3]) : "r"(addr));
}
__device__ __forceinline__ void ldsm_x4_t(uint32_t* r, uint32_t addr) {
    asm volatile("ldmatrix.sync.aligned.m8n8.x4.trans.shared.b16 {%0,%1,%2,%3}, [%4];"
                 : "=r"(r[0]), "=r"(r[1]), "=r"(r[2]), "=r"(r[3]) : "r"(addr));
}
// fp16 mma
__device__ __forceinline__ void mma16816h(float* c, const uint32_t* a,
                                          uint32_t b0, uint32_t b1) {
    asm volatile(
        "mma.sync.aligned.m16n8k16.row.col.f32.f16.f16.f32 "
        "{%0,%1,%2,%3}, {%4,%5,%6,%7}, {%8,%9}, {%0,%1,%2,%3};"
        : "+f"(c[0]), "+f"(c[1]), "+f"(c[2]), "+f"(c[3])
        : "r"(a[0]), "r"(a[1]), "r"(a[2]), "r"(a[3]), "r"(b0), "r"(b1));
}
// fp16 split + pack
__device__ __forceinline__ void hpsplit(float p0, float p1,
                                        uint32_t& hreg, uint32_t& lreg) {
    __half2 hh = __floats2half2_rn(p0, p1);
    float r0 = p0 - __low2float(hh);
    float r1 = p1 - __high2float(hh);
    __half2 ll = __floats2half2_rn(r0, r1);
    hreg = *reinterpret_cast<uint32_t*>(&hh);
    lreg = *reinterpret_cast<uint32_t*>(&ll);
}
__device__ __forceinline__ uint32_t hpack(float p0, float p1) {
    __half2 hh = __floats2half2_rn(p0, p1);
    return *reinterpret_cast<uint32_t*>(&hh);
}
__device__ __forceinline__ void hsplit(float x, __half& h, __half& l) {
    h = __float2half_rn(x);
    l = __float2half_rn(x - __half2float(h));
}

// ---------------------------------------------------------------------------
// Precision-split conversion: x -> (fp16 hi, fp16 lo)
// ---------------------------------------------------------------------------
__global__ __launch_bounds__(256)
void split_convert(const float* __restrict__ in, __half* __restrict__ h,
                   __half* __restrict__ l, int n)
{
    int i = blockIdx.x * blockDim.x + threadIdx.x;
    if (i < n) {
        __half hi, lo;
        hsplit(in[i], hi, lo);
        h[i] = hi;
        l[i] = lo;
    }
}

// Transpose: Wt[z][n][k] = W_z[k][n]  (single fp16)
__global__ __launch_bounds__(256)
void transpose_w(const float* __restrict__ W0, const float* __restrict__ W1,
                 const float* __restrict__ W2, const float* __restrict__ W3,
                 __half* __restrict__ th)
{
    __shared__ float t[32][33];
    const float* W = (blockIdx.z == 0) ? W0 : (blockIdx.z == 1) ? W1
                   : (blockIdx.z == 2) ? W2 : W3;
    int n0 = blockIdx.x * 32, k0 = blockIdx.y * 32;
    int tx = threadIdx.x & 31, ty = threadIdx.x >> 5;
#pragma unroll
    for (int i = 0; i < 4; i++)
        t[ty + 8 * i][tx] = W[(size_t)(k0 + ty + 8 * i) * EE + n0 + tx];
    __syncthreads();
    size_t base = (size_t)blockIdx.z * EE * EE;
#pragma unroll
    for (int i = 0; i < 4; i++) {
        int row = ty + 8 * i;                 // local n
        th[base + (size_t)(n0 + row) * EE + k0 + tx] = __float2half_rn(t[tx][row]);
    }
}

// ---------------------------------------------------------------------------
// fp16 mma.sync GEMM: C = A @ W + bias.  A = fp16 hi+lo (exact to 2^-22),
// W = single fp16 (error = W rounding ~2^-12).  2 MMAs per k-step.
// CTA 128x128, 8 warps of 32x64, K-chunk 64, 2-stage cp.async, occupancy 2.
// MODE 0: fp32 C[m*EE+n] to fout.
// MODE 1: fused epilogue — bias + RoPE (smem trig table) + single-fp16
//         outputs: q (unscaled), k (x0.125), v -> [B,H,S,D].
// ---------------------------------------------------------------------------
#define KC 64
#define NCH (EE / KC)                 // 12
#define GM_PITCH 144                  // 64 halves = 128B data + 16B pad
#define GM_TILE (128 * GM_PITCH)      // 18432
#define GM_BUF (3 * GM_TILE)          // Ah, Al, B = 55296
#define GM_SMEM (2 * GM_BUF)          // 110592 -> 2 CTAs/SM

template<int MODE>
__global__ __launch_bounds__(256, 2)
void gemm_mma(const __half* __restrict__ Ah, const __half* __restrict__ Al,
              const __half* __restrict__ Wt,
              const float* b0, const float* b1, const float* b2, const float* b3,
              float* fout,
              __half* q16, __half* k16, __half* v16)
{
    extern __shared__ char smem[];
    const uint32_t sb = smem_u32(smem);
    const int tid = threadIdx.x;
    const int wid = tid >> 5, lane = tid & 31;
    const int wm = wid & 3;          // 4 m-groups of 32 rows
    const int wn = wid >> 2;         // 2 n-groups of 64 cols

    const int wsel = (MODE == 1) ? (int)blockIdx.z : 3;
    const float* bias = (wsel == 0) ? b0 : (wsel == 1) ? b1 : (wsel == 2) ? b2 : b3;
    const __half* Bw = Wt + (size_t)wsel * EE * EE;
    const int m0 = blockIdx.y * 128;
    const int n0 = blockIdx.x * 128;

    auto load_chunk = [&](int c) {
        uint32_t buf = sb + (uint32_t)(c & 1) * GM_BUF;
        int k0 = c * KC;
#pragma unroll
        for (int i = 0; i < 4; i++) {
            int idx = tid + i * 256;            // 0..1023
            int row = idx >> 3;                 // 0..127
            int j   = idx & 7;                  // 16B quad (64 halves per row)
            uint32_t off = (uint32_t)(row * GM_PITCH + j * 16);
            size_t ga = (size_t)(m0 + row) * EE + k0 + j * 8;
            size_t gb = (size_t)(n0 + row) * EE + k0 + j * 8;
            cp_async16(buf + 0 * GM_TILE + off, Ah + ga);
            cp_async16(buf + 1 * GM_TILE + off, Al + ga);
            cp_async16(buf + 2 * GM_TILE + off, Bw + gb);
        }
        cp_commit();
    };

    float acc[2][8][4];
#pragma unroll
    for (int mt = 0; mt < 2; mt++)
#pragma unroll
        for (int nt = 0; nt < 8; nt++)
#pragma unroll
            for (int i = 0; i < 4; i++) acc[mt][nt][i] = 0.f;

    load_chunk(0);
    load_chunk(1);

    const int rA = wm * 32 + (lane & 15);
    const int rB = wn * 64 + (lane & 15);
    const uint32_t chalf = (uint32_t)((lane >> 4) * 16);

    for (int c = 0; c < NCH; c++) {
        cp_wait1();            // chunk c resident
        __syncthreads();
        uint32_t buf = sb + (uint32_t)(c & 1) * GM_BUF;

#pragma unroll
        for (int ks = 0; ks < 4; ks++) {
            uint32_t colo = (uint32_t)(ks * 32) + chalf;
            uint32_t ah[2][4], al[2][4], bw[4][4];
#pragma unroll
            for (int mt = 0; mt < 2; mt++) {
                uint32_t off = (uint32_t)((rA + mt * 16) * GM_PITCH) + colo;
                ldsm_x4(ah[mt], buf + 0 * GM_TILE + off);
                ldsm_x4(al[mt], buf + 1 * GM_TILE + off);
            }
#pragma unroll
            for (int p = 0; p < 4; p++) {
                uint32_t off = (uint32_t)((rB + p * 16) * GM_PITCH) + colo;
                ldsm_x4(bw[p], buf + 2 * GM_TILE + off);
            }
#pragma unroll
            for (int mt = 0; mt < 2; mt++)
#pragma unroll
                for (int nt = 0; nt < 8; nt++) {
                    const int p = nt >> 1, q = nt & 1;
                    mma16816h(acc[mt][nt], ah[mt], bw[p][q], bw[p][q + 2]);
                    mma16816h(acc[mt][nt], al[mt], bw[p][q], bw[p][q + 2]);
                }
        }

        __syncthreads();       // all warps done reading slot c&1
        if (c + 2 < NCH) load_chunk(c + 2);
        else cp_commit();
    }

    if (MODE == 0) {
        // plain fp32 epilogue (output projection -> d_out)
        const int mrow0 = m0 + wm * 32;
#pragma unroll
        for (int mt = 0; mt < 2; mt++) {
#pragma unroll
            for (int nt = 0; nt < 8; nt++) {
                int gn = n0 + wn * 64 + nt * 8 + 2 * (lane & 3);
                float2 bv = *(const float2*)&bias[gn];
                int r0 = mrow0 + mt * 16 + (lane >> 2);
                float2 v0 = { acc[mt][nt][0] + bv.x, acc[mt][nt][1] + bv.y };
                float2 v1 = { acc[mt][nt][2] + bv.x, acc[mt][nt][3] + bv.y };
                *(float2*)&fout[(size_t)r0 * EE + gn] = v0;
                *(float2*)&fout[(size_t)(r0 + 8) * EE + gn] = v1;
            }
        }
    } else {
        // fused bias + RoPE + single-fp16 pack epilogue
        __half* dh = (wsel == 0) ? q16 : (wsel == 1) ? k16 : v16;
        const int hh = (int)blockIdx.x * 2 + wn;     // head index
        const int c2 = 2 * (lane & 3);
        const float RC = 0.28782313662425572f;       // ln(10000)/32

        float2* tab = (float2*)smem;                 // reuse dead stage buffers
        if (wsel < 2) {
            cp_wait0();
            __syncthreads();                         // stage buffers now dead
            for (int idx = tid; idx < 128 * 32; idx += 256) {
                int rl = idx >> 5, i = idx & 31;
                int s = (m0 + rl) & (SS - 1);
                float ang = (float)s * expf(-(float)i * RC);
                float sn, cs;
                sincosf(ang, &sn, &cs);
                tab[idx] = make_float2(cs, sn);
            }
            __syncthreads();
        }

#pragma unroll
        for (int mt = 0; mt < 2; mt++) {
#pragma unroll
            for (int rr = 0; rr < 2; rr++) {
                int rloc = wm * 32 + mt * 16 + (lane >> 2) + rr * 8;
                int r = m0 + rloc;
                int b_ = r >> 11, s = r & (SS - 1);
                float vals[8][2];
#pragma unroll
                for (int nt = 0; nt < 8; nt++) {
                    float2 bv = *(const float2*)&bias[hh * 64 + nt * 8 + c2];
                    vals[nt][0] = acc[mt][nt][2 * rr]     + bv.x;
                    vals[nt][1] = acc[mt][nt][2 * rr + 1] + bv.y;
                }
                if (wsel < 2) {
#pragma unroll
                    for (int nt = 0; nt < 4; nt++) {
#pragma unroll
                        for (int cc = 0; cc < 2; cc++) {
                            int i = nt * 8 + c2 + cc;
                            float2 cs = tab[rloc * 32 + i];
                            float x = vals[nt][cc], y = vals[nt + 4][cc];
                            vals[nt][cc]     = x * cs.x - y * cs.y;
                            vals[nt + 4][cc] = y * cs.x + x * cs.y;
                        }
                    }
                    if (wsel == 1) {                 // fold 1/sqrt(D) into K
#pragma unroll
                        for (int nt = 0; nt < 8; nt++) {
                            vals[nt][0] *= 0.125f;
                            vals[nt][1] *= 0.125f;
                        }
                    }
                }
                size_t rowb = ((size_t)(b_ * HH + hh) * SS + s) * DD;
#pragma unroll
                for (int nt = 0; nt < 8; nt++)
                    *(uint32_t*)&dh[rowb + nt * 8 + c2] =
                        hpack(vals[nt][0], vals[nt][1]);
            }
        }
    }
}

// ---------------------------------------------------------------------------
// Tensor-core causal flash attention — all-single-fp16 operands.
// S = Q16·K16 (K pre-scaled by 0.125); O += P16·V16.
// Error budget: Q,K,V,P each contribute ~2^-12 relative; measured-model
// projects ~5.5e-4 total pipeline rel_err (gate 1e-3).
// CTA = 128 Q rows, 8 warps x 16 rows, 64-wide KV double-buffered,
// per-warp tile skip + 16-col strip skip on partial diagonal tiles.
// Output fp16 hi/lo (A-side of the output projection stays exact).
// ---------------------------------------------------------------------------
#define AT_PITCH 144                      // 64 halves = 128B data + 16B pad
#define AT_Q (128 * AT_PITCH)             // 18432 (single Q tile)
#define AT_KV (64 * AT_PITCH)             // 9216 per K/V tile
#define AT_STAGE (2 * AT_KV)              // K, V = 18432
#define AT_SMEM (AT_Q + 2 * AT_STAGE)     // 55296

__global__ __launch_bounds__(256, 2)
void attn_mma(const __half* __restrict__ q16, const __half* __restrict__ k16,
              const __half* __restrict__ v16,
              __half* __restrict__ oh, __half* __restrict__ ol)
{
    extern __shared__ char smem[];
    const uint32_t sb = smem_u32(smem);
    const int tid = threadIdx.x;
    const int wid = tid >> 5, lane = tid & 31;

    const int mtile = (int)(gridDim.x - 1 - blockIdx.x);   // heavy CTAs first
    const int bh = blockIdx.y;
    const int m0 = mtile * 128;
    const int ntmax = 2 * mtile + 1;
    const size_t hbase = (size_t)bh * SS * DD;
    const __half* qp = q16 + hbase;
    const __half* kp = k16 + hbase;
    const __half* vp = v16 + hbase;

    // ---- load Q tile ----
#pragma unroll
    for (int i = 0; i < 4; i++) {
        int cid = tid + i * 256;           // 0..1023
        int row = cid >> 3;
        int j   = cid & 7;
        uint32_t off = (uint32_t)(row * AT_PITCH + j * 16);
        cp_async16(sb + off, qp + (size_t)(m0 + row) * DD + j * 8);
    }
    cp_commit();

    auto load_kv = [&](int t) {
        if (t <= ntmax) {
            uint32_t base = sb + AT_Q + (uint32_t)(t & 1) * AT_STAGE;
            int n0 = t * 64;
#pragma unroll
            for (int i = 0; i < 2; i++) {
                int cid = tid + i * 256;       // 0..511
                int row = cid >> 3;
                int j   = cid & 7;
                uint32_t off = (uint32_t)(row * AT_PITCH + j * 16);
                size_t g = (size_t)(n0 + row) * DD + j * 8;
                cp_async16(base + 0 * AT_KV + off, kp + g);
                cp_async16(base + 1 * AT_KV + off, vp + g);
            }
        }
        cp_commit();
    };
    load_kv(0);
    load_kv(1);

    float oacc[8][4];
#pragma unroll
    for (int d = 0; d < 8; d++)
#pragma unroll
        for (int j = 0; j < 4; j++) oacc[d][j] = 0.f;
    float mi0 = -1e30f, mi1 = -1e30f, li0 = 0.f, li1 = 0.f;
    uint32_t qf[4][4];

    const int wr0 = m0 + wid * 16;     // warp's first global Q row

    for (int nt = 0; nt <= ntmax; nt++) {
        cp_wait1();
        __syncthreads();               // stage nt (and Q at nt=0) visible

        if (nt == 0) {                 // load Q fragments once
#pragma unroll
            for (int kc = 0; kc < 4; kc++) {
                uint32_t a = sb + (uint32_t)((wid * 16 + (lane & 15)) * AT_PITCH)
                           + (uint32_t)(kc * 32) + (uint32_t)((lane >> 4) * 16);
                ldsm_x4(qf[kc], a);
            }
        }

        const int n0 = nt * 64;
        const int climit = wr0 + 15;   // last valid column for this warp
        if (n0 <= climit) {            // warp has unmasked rows in this tile
            const bool part = (n0 + 63 > wr0);   // partial (diagonal band) tile
            const uint32_t kvb = sb + AT_Q + (uint32_t)(nt & 1) * AT_STAGE;

            // ---- S = Q K; skip fully-masked 16-col strips ----
            float sacc[8][4];
#pragma unroll
            for (int t8 = 0; t8 < 8; t8++)
#pragma unroll
                for (int j = 0; j < 4; j++) sacc[t8][j] = 0.f;

#pragma unroll
            for (int kc = 0; kc < 4; kc++) {
                uint32_t colo = (uint32_t)(kc * 32) + (uint32_t)((lane >> 4) * 16);
#pragma unroll
                for (int st = 0; st < 4; st++) {
                    if (!part || n0 + st * 16 <= climit) {
                        uint32_t a = kvb + (uint32_t)((st * 16 + (lane & 15)) * AT_PITCH) + colo;
                        uint32_t k4[4];
                        ldsm_x4(k4, a);
                        mma16816h(sacc[2 * st],     qf[kc], k4[0], k4[2]);
                        mma16816h(sacc[2 * st + 1], qf[kc], k4[1], k4[3]);
                    }
                }
            }

            // ---- causal mask (partial tiles only; skipped strips -> -inf) ----
            const int rr0 = wr0 + (lane >> 2);
            if (part) {
#pragma unroll
                for (int t8 = 0; t8 < 8; t8++) {
                    int c0 = n0 + t8 * 8 + 2 * (lane & 3);
                    if (c0     > rr0)     sacc[t8][0] = -1e30f;
                    if (c0 + 1 > rr0)     sacc[t8][1] = -1e30f;
                    if (c0     > rr0 + 8) sacc[t8][2] = -1e30f;
                    if (c0 + 1 > rr0 + 8) sacc[t8][3] = -1e30f;
                }
            }

            // ---- online softmax (rows lane/4 and lane/4+8) ----
            float mx0 = -1e30f, mx1 = -1e30f;
#pragma unroll
            for (int t8 = 0; t8 < 8; t8++) {
                mx0 = fmaxf(mx0, fmaxf(sacc[t8][0], sacc[t8][1]));
                mx1 = fmaxf(mx1, fmaxf(sacc[t8][2], sacc[t8][3]));
            }
            mx0 = fmaxf(mx0, __shfl_xor_sync(0xffffffffu, mx0, 1));
            mx0 = fmaxf(mx0, __shfl_xor_sync(0xffffffffu, mx0, 2));
            mx1 = fmaxf(mx1, __shfl_xor_sync(0xffffffffu, mx1, 1));
            mx1 = fmaxf(mx1, __shfl_xor_sync(0xffffffffu, mx1, 2));
            float mn0 = fmaxf(mi0, mx0), mn1 = fmaxf(mi1, mx1);
            float al0 = __expf(mi0 - mn0), al1 = __expf(mi1 - mn1);
            mi0 = mn0; mi1 = mn1;
            float s0 = 0.f, s1 = 0.f;
#pragma unroll
            for (int t8 = 0; t8 < 8; t8++) {
                float p0 = __expf(sacc[t8][0] - mn0);
                float p1 = __expf(sacc[t8][1] - mn0);
                float p2 = __expf(sacc[t8][2] - mn1);
                float p3 = __expf(sacc[t8][3] - mn1);
                sacc[t8][0] = p0; sacc[t8][1] = p1;
                sacc[t8][2] = p2; sacc[t8][3] = p3;
                s0 += p0 + p1; s1 += p2 + p3;
            }
            li0 = li0 * al0 + s0;        // lane-partial row sums
            li1 = li1 * al1 + s1;
#pragma unroll
            for (int d = 0; d < 8; d++) {
                oacc[d][0] *= al0; oacc[d][1] *= al0;
                oacc[d][2] *= al1; oacc[d][3] *= al1;
            }

            // ---- P -> single fp16 A-fragments ----
            uint32_t aP[4][4];
#pragma unroll
            for (int kc = 0; kc < 4; kc++) {
                aP[kc][0] = hpack(sacc[2 * kc][0],     sacc[2 * kc][1]);
                aP[kc][1] = hpack(sacc[2 * kc][2],     sacc[2 * kc][3]);
                aP[kc][2] = hpack(sacc[2 * kc + 1][0], sacc[2 * kc + 1][1]);
                aP[kc][3] = hpack(sacc[2 * kc + 1][2], sacc[2 * kc + 1][3]);
            }

            // ---- O += P V; skip all-masked strips ----
            const uint32_t vbb = kvb + 1 * AT_KV;
#pragma unroll
            for (int kc = 0; kc < 4; kc++) {
                if (!part || n0 + kc * 16 <= climit) {
#pragma unroll
                    for (int vp_ = 0; vp_ < 4; vp_++) {
                        uint32_t off = (uint32_t)((kc * 16 + (lane & 15)) * AT_PITCH)
                                     + (uint32_t)(vp_ * 32) + (uint32_t)((lane >> 4) * 16);
                        uint32_t v4[4];
                        ldsm_x4_t(v4, vbb + off);
                        mma16816h(oacc[2 * vp_],     aP[kc], v4[0], v4[1]);
                        mma16816h(oacc[2 * vp_ + 1], aP[kc], v4[2], v4[3]);
                    }
                }
            }
        }

        __syncthreads();               // all warps done reading slot nt&1
        load_kv(nt + 2);
    }

    // ---- normalize + write split fp16 output [m][E] at cols h*64.. ----
    li0 += __shfl_xor_sync(0xffffffffu, li0, 1);
    li0 += __shfl_xor_sync(0xffffffffu, li0, 2);
    li1 += __shfl_xor_sync(0xffffffffu, li1, 1);
    li1 += __shfl_xor_sync(0xffffffffu, li1, 2);
    const float inv0 = 1.f / li0, inv1 = 1.f / li1;

    const int b_ = bh / HH, h_ = bh % HH;
    const int r0g = m0 + wid * 16 + (lane >> 2);
#pragma unroll
    for (int dt = 0; dt < 8; dt++) {
        int col = h_ * 64 + dt * 8 + 2 * (lane & 3);
        size_t o0 = (size_t)(b_ * SS + r0g) * EE + col;
        size_t o1 = (size_t)(b_ * SS + r0g + 8) * EE + col;
        uint32_t hreg, lreg;
        hpsplit(oacc[dt][0] * inv0, oacc[dt][1] * inv0, hreg, lreg);
        *(uint32_t*)&oh[o0] = hreg;
        *(uint32_t*)&ol[o0] = lreg;
        hpsplit(oacc[dt][2] * inv1, oacc[dt][3] * inv1, hreg, lreg);
        *(uint32_t*)&oh[o1] = hreg;
        *(uint32_t*)&ol[o1] = lreg;
    }
}

// ---------------------------------------------------------------------------
extern "C" void kernel_launch(void* const* d_in, const int* in_sizes, int n_in,
                              void* d_out, int out_size)
{
    (void)in_sizes; (void)n_in; (void)out_size;
    const float* x  = (const float*)d_in[0];
    const float* Wq = (const float*)d_in[1];
    const float* bq = (const float*)d_in[2];
    const float* Wk = (const float*)d_in[3];
    const float* bk = (const float*)d_in[4];
    const float* Wv = (const float*)d_in[5];
    const float* bv = (const float*)d_in[6];
    const float* Wp = (const float*)d_in[7];
    const float* bp = (const float*)d_in[8];

    __half *ah, *al, *wt, *q16, *k16, *v16;
    cudaGetSymbolAddress((void**)&ah,  g_ah);
    cudaGetSymbolAddress((void**)&al,  g_al);
    cudaGetSymbolAddress((void**)&wt,  g_wt);
    cudaGetSymbolAddress((void**)&q16, g_q16);
    cudaGetSymbolAddress((void**)&k16, g_k16);
    cudaGetSymbolAddress((void**)&v16, g_v16);

    cudaFuncSetAttribute(gemm_mma<1>,
                         cudaFuncAttributeMaxDynamicSharedMemorySize, GM_SMEM);
    cudaFuncSetAttribute(gemm_mma<0>,
                         cudaFuncAttributeMaxDynamicSharedMemorySize, GM_SMEM);
    cudaFuncSetAttribute(attn_mma,
                         cudaFuncAttributeMaxDynamicSharedMemorySize, AT_SMEM);

    // Split x into fp16 hi/lo; transpose weights to fp16 [n][k]
    split_convert<<<(MT * EE + 255) / 256, 256>>>(x, ah, al, MT * EE);
    transpose_w<<<dim3(EE / 32, EE / 32, 4), 256>>>(Wq, Wk, Wv, Wp, wt);

    // Fused Q/K/V projections + bias + RoPE + fp16 pack -> [B,H,S,D]
    gemm_mma<1><<<dim3(EE / 128, MT / 128, 3), 256, GM_SMEM>>>(
        ah, al, wt, bq, bk, bv, nullptr, nullptr, q16, k16, v16);

    // fp16 tensor-core causal flash attention -> fp16 hi/lo [B,S,E] (ah/al)
    attn_mma<<<dim3(SS / 128, BB * HH), 256, AT_SMEM>>>(
        q16, k16, v16, ah, al);

    // Output projection -> d_out
    gemm_mma<0><<<dim3(EE / 128, MT / 128, 1), 256, GM_SMEM>>>(
        ah, al, wt, nullptr, nullptr, nullptr, bp, (float*)d_out,
        nullptr, nullptr, nullptr);
}